// round 5
// baseline (speedup 1.0000x reference)
#include <cuda_runtime.h>
#include <math.h>
#include <stdint.h>

// Problem constants
#define BB   64
#define HH   28
#define WW   28
#define CC   384
#define TT   784      // HH*WW
#define HK   13       // (28-3)/2+1
#define TK   169      // 13*13
#define NHEAD 6
#define DD   64
#define EPSV 1e-3f

// Scratch (device globals). All intermediate activations hold TF32 bit patterns.
__device__ float g_qc[(size_t)BB*TT*CC];
__device__ float g_kc[(size_t)BB*TK*CC];
__device__ float g_vc[(size_t)BB*TK*CC];
__device__ float g_Q [(size_t)BB*TT*CC];
__device__ float g_K [(size_t)BB*TK*CC];
__device__ float g_V [(size_t)BB*TK*CC];
__device__ float g_O [(size_t)BB*TT*CC];
__device__ float g_Wqt[(size_t)CC*CC];
__device__ float g_Wkt[(size_t)CC*CC];
__device__ float g_Wvt[(size_t)CC*CC];
__device__ float g_Wot[(size_t)CC*CC];

// ---------------------------------------------------------------------------
// TF32 / async helpers
// ---------------------------------------------------------------------------
__device__ __forceinline__ uint32_t f2tf(float x) {
    uint32_t r;
    asm("cvt.rna.tf32.f32 %0, %1;" : "=r"(r) : "f"(x));
    return r;
}

__device__ __forceinline__ void mma8(float* c, const uint32_t* a, const uint32_t* b) {
    asm volatile(
        "mma.sync.aligned.m16n8k8.row.col.f32.tf32.tf32.f32 "
        "{%0,%1,%2,%3}, {%4,%5,%6,%7}, {%8,%9}, {%0,%1,%2,%3};"
        : "+f"(c[0]), "+f"(c[1]), "+f"(c[2]), "+f"(c[3])
        : "r"(a[0]), "r"(a[1]), "r"(a[2]), "r"(a[3]), "r"(b[0]), "r"(b[1]));
}

__device__ __forceinline__ void cp16(uint32_t dst_smem, const void* src, bool pred) {
    int sz = pred ? 16 : 0;
    asm volatile("cp.async.ca.shared.global [%0], [%1], 16, %2;"
                 :: "r"(dst_smem), "l"(src), "r"(sz));
}
__device__ __forceinline__ void cp_commit() { asm volatile("cp.async.commit_group;"); }

// ---------------------------------------------------------------------------
// One-shot weight conversion: fp32 -> tf32 bits (4 matrices, 384x384 each)
// ---------------------------------------------------------------------------
__global__ void cvt_weights(const float* __restrict__ Wq, const float* __restrict__ Wk,
                            const float* __restrict__ Wv, const float* __restrict__ Wo)
{
    int i = blockIdx.x * blockDim.x + threadIdx.x;
    if (i >= CC*CC) return;
    g_Wqt[i] = __uint_as_float(f2tf(Wq[i]));
    g_Wkt[i] = __uint_as_float(f2tf(Wk[i]));
    g_Wvt[i] = __uint_as_float(f2tf(Wv[i]));
    g_Wot[i] = __uint_as_float(f2tf(Wo[i]));
}

// ---------------------------------------------------------------------------
// Depthwise 3x3 conv (stride 1, SAME) + BN, q path. Output = tf32 bits.
// ---------------------------------------------------------------------------
__global__ void dwbn_q_kernel(const float* __restrict__ x,
                              const float* __restrict__ w,
                              const float* __restrict__ gamma,
                              const float* __restrict__ beta,
                              const float* __restrict__ mean,
                              const float* __restrict__ var,
                              float* __restrict__ out)
{
    int c  = threadIdx.x;
    int sp = blockIdx.x;
    int b  = sp / TT;
    int t  = sp - b * TT;
    int y  = t / WW;
    int xw = t - y * WW;

    float acc = 0.f;
#pragma unroll
    for (int dy = 0; dy < 3; ++dy) {
        int yy = y + dy - 1;
        if (yy < 0 || yy >= HH) continue;
#pragma unroll
        for (int dx = 0; dx < 3; ++dx) {
            int xx = xw + dx - 1;
            if (xx < 0 || xx >= WW) continue;
            acc += x[((size_t)b*TT + yy*WW + xx)*CC + c] * w[(dy*3+dx)*CC + c];
        }
    }
    float sc = gamma[c] * rsqrtf(var[c] + EPSV);
    out[(size_t)sp*CC + c] = __uint_as_float(f2tf(sc * (acc - mean[c]) + beta[c]));
}

// ---------------------------------------------------------------------------
// Depthwise 3x3 conv (stride 2, VALID) + BN, fused k+v. Output = tf32 bits.
// ---------------------------------------------------------------------------
__global__ void dwbn_kv_kernel(const float* __restrict__ x,
                               const float* __restrict__ wk,
                               const float* __restrict__ kg,
                               const float* __restrict__ kb,
                               const float* __restrict__ km,
                               const float* __restrict__ kvv,
                               const float* __restrict__ wv,
                               const float* __restrict__ vg,
                               const float* __restrict__ vb,
                               const float* __restrict__ vm,
                               const float* __restrict__ vvv,
                               float* __restrict__ outk,
                               float* __restrict__ outv)
{
    int c  = threadIdx.x;
    int sp = blockIdx.x;
    int b  = sp / TK;
    int t  = sp - b * TK;
    int y  = t / HK;
    int xw = t - y * HK;

    float ak = 0.f, av = 0.f;
#pragma unroll
    for (int dy = 0; dy < 3; ++dy) {
#pragma unroll
        for (int dx = 0; dx < 3; ++dx) {
            float xv = x[((size_t)b*TT + (2*y+dy)*WW + (2*xw+dx))*CC + c];
            ak += xv * wk[(dy*3+dx)*CC + c];
            av += xv * wv[(dy*3+dx)*CC + c];
        }
    }
    float sck = kg[c] * rsqrtf(kvv[c] + EPSV);
    float scv = vg[c] * rsqrtf(vvv[c] + EPSV);
    outk[(size_t)sp*CC + c] = __uint_as_float(f2tf(sck * (ak - km[c]) + kb[c]));
    outv[(size_t)sp*CC + c] = __uint_as_float(f2tf(scv * (av - vm[c]) + vb[c]));
}

// ---------------------------------------------------------------------------
// TF32 GEMM v3: inputs are tf32 bit patterns; NO cvt in the main loop.
// C[M,384] = A @ B (+bias). bias!=null -> fp32 output; else tf32-bits output.
// 256 threads (8 warps, 2m x 4n), block 128x128, warp 64x32, BK=16,
// cp.async double-buffered.
// ---------------------------------------------------------------------------
#define GBM 128
#define GBN 128
#define GBK 16
#define ASTR 20
#define BSTR 136
#define NT   (CC/GBK)   // 24

__global__ __launch_bounds__(256, 2)
void gemm_tf32(const float* __restrict__ A, const float* __restrict__ Bm,
               const float* __restrict__ bias, float* __restrict__ Cm, int M)
{
    __shared__ uint32_t As[2][GBM*ASTR];
    __shared__ uint32_t Bs[2][GBK*BSTR];

    int tid  = threadIdx.x;
    int warp = tid >> 5;
    int lane = tid & 31;
    int g    = lane >> 2;
    int tg   = lane & 3;
    int bm   = blockIdx.x * GBM;
    int bn   = blockIdx.y * GBN;
    int wm   = (warp >> 2) * 64;
    int wn   = (warp & 3) * 32;

    int a_r = tid >> 2;           // 0..63 (x2 -> 128 rows)
    int a_q = (tid & 3) * 4;
    int b_r = tid >> 4;           // 0..15
    int b_q = (tid & 15) * 4;     // (x2 -> 128 cols)

    uint32_t sA[2], sB[2];
    sA[0] = (uint32_t)__cvta_generic_to_shared(&As[0][0]);
    sA[1] = (uint32_t)__cvta_generic_to_shared(&As[1][0]);
    sB[0] = (uint32_t)__cvta_generic_to_shared(&Bs[0][0]);
    sB[1] = (uint32_t)__cvta_generic_to_shared(&Bs[1][0]);

    float acc[4][4][4];
#pragma unroll
    for (int mf = 0; mf < 4; ++mf)
#pragma unroll
        for (int nf = 0; nf < 4; ++nf)
#pragma unroll
            for (int c = 0; c < 4; ++c) acc[mf][nf][c] = 0.f;

    auto load_stage = [&](int t, int buf) {
#pragma unroll
        for (int i = 0; i < 2; ++i) {
            int r  = i*64 + a_r;
            int gr = bm + r;
            bool p = (gr < M);
            const float* src = &A[(size_t)(p ? gr : 0)*CC + t*GBK + a_q];
            cp16(sA[buf] + (uint32_t)(r*ASTR + a_q)*4u, src, p);
        }
#pragma unroll
        for (int i = 0; i < 2; ++i) {
            int col = i*64 + b_q;
            const float* src = &Bm[(size_t)(t*GBK + b_r)*CC + bn + col];
            cp16(sB[buf] + (uint32_t)(b_r*BSTR + col)*4u, src, true);
        }
        cp_commit();
    };

    load_stage(0, 0);

    for (int t = 0; t < NT; ++t) {
        int buf = t & 1;
        if (t + 1 < NT) {
            load_stage(t + 1, buf ^ 1);
            asm volatile("cp.async.wait_group 1;");
        } else {
            asm volatile("cp.async.wait_group 0;");
        }
        __syncthreads();

        const uint32_t* Ab = As[buf];
        const uint32_t* Bb = Bs[buf];
#pragma unroll
        for (int kk = 0; kk < GBK; kk += 8) {
            uint32_t af[4][4];
#pragma unroll
            for (int mf = 0; mf < 4; ++mf) {
                int rb = wm + mf*16;
                af[mf][0] = Ab[(rb + g    )*ASTR + kk + tg    ];
                af[mf][1] = Ab[(rb + g + 8)*ASTR + kk + tg    ];
                af[mf][2] = Ab[(rb + g    )*ASTR + kk + tg + 4];
                af[mf][3] = Ab[(rb + g + 8)*ASTR + kk + tg + 4];
            }
#pragma unroll
            for (int nf = 0; nf < 4; ++nf) {
                uint32_t bf[2];
                bf[0] = Bb[(kk + tg    )*BSTR + wn + nf*8 + g];
                bf[1] = Bb[(kk + tg + 4)*BSTR + wn + nf*8 + g];
#pragma unroll
                for (int mf = 0; mf < 4; ++mf)
                    mma8(acc[mf][nf], af[mf], bf);
            }
        }
        __syncthreads();
    }

    // Epilogue: fp32 (+bias) for the final projection, tf32 bits otherwise.
#pragma unroll
    for (int mf = 0; mf < 4; ++mf) {
#pragma unroll
        for (int i = 0; i < 2; ++i) {
            int gr = bm + wm + mf*16 + g + i*8;
            if (gr >= M) continue;
#pragma unroll
            for (int nf = 0; nf < 4; ++nf) {
                int col = bn + wn + nf*8 + tg*2;
                float2 v;
                if (bias) {
                    v.x = acc[mf][nf][i*2 + 0] + bias[col];
                    v.y = acc[mf][nf][i*2 + 1] + bias[col+1];
                } else {
                    v.x = __uint_as_float(f2tf(acc[mf][nf][i*2 + 0]));
                    v.y = __uint_as_float(f2tf(acc[mf][nf][i*2 + 1]));
                }
                *(float2*)&Cm[(size_t)gr*CC + col] = v;
            }
        }
    }
}

// ---------------------------------------------------------------------------
// Attention v4: inputs Q/K/V are tf32 bits (no cvt on load).
// Register-resident S/P, 8 warps x 16 q-rows = 128 rows/block.
// smem: K^T (64x176, stride 184) + V (176x64, stride 72) = 97.8KB.
// ---------------------------------------------------------------------------
#define JP    176
#define NKC   22     // JP/8
#define KSTR  184
#define VSTR  72

__global__ __launch_bounds__(256, 2)
void attn_tf32(const float* __restrict__ Q, const float* __restrict__ K,
               const float* __restrict__ V, float* __restrict__ O)
{
    extern __shared__ uint32_t sm[];
    uint32_t* Ks = sm;               // [d][j] 64*184
    uint32_t* Vs = sm + 64*KSTR;     // [j][d] 176*72

    int tid  = threadIdx.x;
    int warp = tid >> 5;
    int lane = tid & 31;
    int g    = lane >> 2;
    int tg   = lane & 3;
    int bh   = blockIdx.y;
    int b    = bh / NHEAD;
    int h    = bh - b * NHEAD;
    int row0 = blockIdx.x * 128;
    const float scale = rsqrtf((float)CC);

    // Cooperative K^T / V load (already tf32 bits), zero-pad j >= TK
    for (int idx = tid; idx < JP*16; idx += 256) {
        int j = idx >> 4, d = (idx & 15) << 2;
        float4 kv = make_float4(0.f,0.f,0.f,0.f);
        float4 vv = make_float4(0.f,0.f,0.f,0.f);
        if (j < TK) {
            kv = *(const float4*)&K[((size_t)b*TK + j)*CC + h*DD + d];
            vv = *(const float4*)&V[((size_t)b*TK + j)*CC + h*DD + d];
        }
        Ks[(d+0)*KSTR + j] = __float_as_uint(kv.x);
        Ks[(d+1)*KSTR + j] = __float_as_uint(kv.y);
        Ks[(d+2)*KSTR + j] = __float_as_uint(kv.z);
        Ks[(d+3)*KSTR + j] = __float_as_uint(kv.w);
        Vs[j*VSTR + d + 0] = __float_as_uint(vv.x);
        Vs[j*VSTR + d + 1] = __float_as_uint(vv.y);
        Vs[j*VSTR + d + 2] = __float_as_uint(vv.z);
        Vs[j*VSTR + d + 3] = __float_as_uint(vv.w);
    }
    __syncthreads();

    // ---- S = Q K^T ----
    int r0 = row0 + warp * 16;
    const float* Qb = Q + (size_t)b*TT*CC + (size_t)h*DD;

    float p[NKC][4];
#pragma unroll
    for (int ni = 0; ni < NKC; ++ni)
#pragma unroll
        for (int c = 0; c < 4; ++c) p[ni][c] = 0.f;

#pragma unroll
    for (int kc = 0; kc < 8; ++kc) {
        int kk = kc * 8;
        int ra = r0 + g, rb = r0 + g + 8;
        uint32_t af[4];
        af[0] = __float_as_uint((ra < TT) ? Qb[(size_t)ra*CC + kk + tg    ] : 0.f);
        af[1] = __float_as_uint((rb < TT) ? Qb[(size_t)rb*CC + kk + tg    ] : 0.f);
        af[2] = __float_as_uint((ra < TT) ? Qb[(size_t)ra*CC + kk + tg + 4] : 0.f);
        af[3] = __float_as_uint((rb < TT) ? Qb[(size_t)rb*CC + kk + tg + 4] : 0.f);
#pragma unroll
        for (int ni = 0; ni < NKC; ++ni) {
            uint32_t bf[2];
            bf[0] = Ks[(kk + tg    )*KSTR + ni*8 + g];
            bf[1] = Ks[(kk + tg + 4)*KSTR + ni*8 + g];
            mma8(p[ni], af, bf);
        }
    }

    // ---- scale + mask + softmax in registers ----
    float m0 = -1e30f, m1 = -1e30f;
#pragma unroll
    for (int ni = 0; ni < NKC; ++ni) {
        int c0 = ni*8 + 2*tg, c1 = c0 + 1;
        p[ni][0] = (c0 < TK) ? p[ni][0]*scale : -1e30f;
        p[ni][1] = (c1 < TK) ? p[ni][1]*scale : -1e30f;
        p[ni][2] = (c0 < TK) ? p[ni][2]*scale : -1e30f;
        p[ni][3] = (c1 < TK) ? p[ni][3]*scale : -1e30f;
        m0 = fmaxf(m0, fmaxf(p[ni][0], p[ni][1]));
        m1 = fmaxf(m1, fmaxf(p[ni][2], p[ni][3]));
    }
    m0 = fmaxf(m0, __shfl_xor_sync(~0u, m0, 1));
    m0 = fmaxf(m0, __shfl_xor_sync(~0u, m0, 2));
    m1 = fmaxf(m1, __shfl_xor_sync(~0u, m1, 1));
    m1 = fmaxf(m1, __shfl_xor_sync(~0u, m1, 2));

    float s0 = 0.f, s1 = 0.f;
#pragma unroll
    for (int ni = 0; ni < NKC; ++ni) {
        p[ni][0] = __expf(p[ni][0] - m0);
        p[ni][1] = __expf(p[ni][1] - m0);
        p[ni][2] = __expf(p[ni][2] - m1);
        p[ni][3] = __expf(p[ni][3] - m1);
        s0 += p[ni][0] + p[ni][1];
        s1 += p[ni][2] + p[ni][3];
    }
    s0 += __shfl_xor_sync(~0u, s0, 1);
    s0 += __shfl_xor_sync(~0u, s0, 2);
    s1 += __shfl_xor_sync(~0u, s1, 1);
    s1 += __shfl_xor_sync(~0u, s1, 2);
    float i0 = 1.f / s0, i1 = 1.f / s1;

#pragma unroll
    for (int ni = 0; ni < NKC; ++ni) {
        p[ni][0] = __uint_as_float(f2tf(p[ni][0] * i0));
        p[ni][1] = __uint_as_float(f2tf(p[ni][1] * i0));
        p[ni][2] = __uint_as_float(f2tf(p[ni][2] * i1));
        p[ni][3] = __uint_as_float(f2tf(p[ni][3] * i1));
    }

    // ---- O = P V : two 32-col halves; output tf32 bits for final GEMM ----
    int srcA = (lane & ~3) | (tg >> 1);
    int srcB = srcA + 2;
    int odd  = tg & 1;

#pragma unroll
    for (int half = 0; half < 2; ++half) {
        float oacc[4][4];
#pragma unroll
        for (int nf = 0; nf < 4; ++nf)
#pragma unroll
            for (int c = 0; c < 4; ++c) oacc[nf][c] = 0.f;

#pragma unroll
        for (int kc = 0; kc < NKC; ++kc) {
            float x0 = __shfl_sync(~0u, p[kc][0], srcA);
            float x1 = __shfl_sync(~0u, p[kc][1], srcA);
            float y0 = __shfl_sync(~0u, p[kc][0], srcB);
            float y1 = __shfl_sync(~0u, p[kc][1], srcB);
            float z0 = __shfl_sync(~0u, p[kc][2], srcA);
            float z1 = __shfl_sync(~0u, p[kc][3], srcA);
            float w0 = __shfl_sync(~0u, p[kc][2], srcB);
            float w1 = __shfl_sync(~0u, p[kc][3], srcB);
            uint32_t af[4];
            af[0] = __float_as_uint(odd ? x1 : x0);
            af[1] = __float_as_uint(odd ? z1 : z0);
            af[2] = __float_as_uint(odd ? y1 : y0);
            af[3] = __float_as_uint(odd ? w1 : w0);

            int kk = kc * 8;
#pragma unroll
            for (int nf = 0; nf < 4; ++nf) {
                uint32_t bf[2];
                bf[0] = Vs[(kk + tg    )*VSTR + half*32 + nf*8 + g];
                bf[1] = Vs[(kk + tg + 4)*VSTR + half*32 + nf*8 + g];
                mma8(oacc[nf], af, bf);
            }
        }

#pragma unroll
        for (int nf = 0; nf < 4; ++nf) {
#pragma unroll
            for (int i = 0; i < 2; ++i) {
                int gr = r0 + g + i*8;
                if (gr >= TT) continue;
                int col = h*DD + half*32 + nf*8 + tg*2;
                float2 v;
                v.x = __uint_as_float(f2tf(oacc[nf][i*2 + 0]));
                v.y = __uint_as_float(f2tf(oacc[nf][i*2 + 1]));
                *(float2*)&O[((size_t)b*TT + gr)*CC + col] = v;
            }
        }
    }
}

static const int ATTN_SMEM = (64*KSTR + JP*VSTR) * (int)sizeof(uint32_t);  // 97792

extern "C" void kernel_launch(void* const* d_in, const int* in_sizes, int n_in,
                              void* d_out, int out_size)
{
    (void)in_sizes; (void)n_in; (void)out_size;
    const float* x   = (const float*)d_in[0];
    const float* wq  = (const float*)d_in[1];
    const float* qg  = (const float*)d_in[2];
    const float* qb  = (const float*)d_in[3];
    const float* qm  = (const float*)d_in[4];
    const float* qv  = (const float*)d_in[5];
    const float* wk  = (const float*)d_in[6];
    const float* kg  = (const float*)d_in[7];
    const float* kb  = (const float*)d_in[8];
    const float* km  = (const float*)d_in[9];
    const float* kv_ = (const float*)d_in[10];
    const float* wv  = (const float*)d_in[11];
    const float* vg  = (const float*)d_in[12];
    const float* vb  = (const float*)d_in[13];
    const float* vm  = (const float*)d_in[14];
    const float* vv_ = (const float*)d_in[15];
    const float* Wq  = (const float*)d_in[16];
    const float* Wk  = (const float*)d_in[17];
    const float* Wv  = (const float*)d_in[18];
    const float* Wo  = (const float*)d_in[19];
    const float* bo  = (const float*)d_in[20];
    float* out = (float*)d_out;

    float *qc, *kc, *vc, *Qp, *Kp, *Vp, *Op, *Wqt, *Wkt, *Wvt, *Wot;
    cudaGetSymbolAddress((void**)&qc, g_qc);
    cudaGetSymbolAddress((void**)&kc, g_kc);
    cudaGetSymbolAddress((void**)&vc, g_vc);
    cudaGetSymbolAddress((void**)&Qp, g_Q);
    cudaGetSymbolAddress((void**)&Kp, g_K);
    cudaGetSymbolAddress((void**)&Vp, g_V);
    cudaGetSymbolAddress((void**)&Op, g_O);
    cudaGetSymbolAddress((void**)&Wqt, g_Wqt);
    cudaGetSymbolAddress((void**)&Wkt, g_Wkt);
    cudaGetSymbolAddress((void**)&Wvt, g_Wvt);
    cudaGetSymbolAddress((void**)&Wot, g_Wot);

    // 0. weight conversion (tiny)
    cvt_weights<<<(CC*CC + 255)/256, 256>>>(Wq, Wk, Wv, Wo);

    // 1. conv projections (emit tf32 bits)
    dwbn_q_kernel <<<BB*TT, CC>>>(x, wq, qg, qb, qm, qv, qc);
    dwbn_kv_kernel<<<BB*TK, CC>>>(x, wk, kg, kb, km, kv_, wv, vg, vb, vm, vv_, kc, vc);

    // 2. dense projections (no cvt in main loop)
    const int MQ = BB*TT;   // 50176
    const int MK = BB*TK;   // 10816
    dim3 gq((MQ + GBM - 1)/GBM, CC/GBN);   // 392 x 3
    dim3 gk((MK + GBM - 1)/GBM, CC/GBN);   // 85 x 3
    gemm_tf32<<<gq, 256>>>(qc, Wqt, nullptr, Qp, MQ);
    gemm_tf32<<<gk, 256>>>(kc, Wkt, nullptr, Kp, MK);
    gemm_tf32<<<gk, 256>>>(vc, Wvt, nullptr, Vp, MK);

    // 3. attention
    cudaFuncSetAttribute(attn_tf32, cudaFuncAttributeMaxDynamicSharedMemorySize, ATTN_SMEM);
    dim3 ga((TT + 127)/128, BB*NHEAD);   // 7 x 384
    attn_tf32<<<ga, 256, ATTN_SMEM>>>(Qp, Kp, Vp, Op);

    // 4. output projection (+bias, fp32 out)
    gemm_tf32<<<gq, 256>>>(Op, Wot, bo, out, MQ);
}

// round 6
// speedup vs baseline: 1.3437x; 1.3437x over previous
#include <cuda_runtime.h>
#include <cuda_fp16.h>
#include <math.h>
#include <stdint.h>

// Problem constants
#define BB   64
#define HH   28
#define WW   28
#define CC   384
#define TT   784      // HH*WW
#define HK   13       // (28-3)/2+1
#define TK   169      // 13*13
#define NHEAD 6
#define DD   64
#define EPSV 1e-3f
#define CW   (CC/2)   // 192 half2-words per row

// Scratch (device globals). Activations in fp16; weights in k-paired [n][k/2].
__device__ __half  g_qc[(size_t)BB*TT*CC];
__device__ __half  g_kc[(size_t)BB*TK*CC];
__device__ __half  g_vc[(size_t)BB*TK*CC];
__device__ __half  g_Q [(size_t)BB*TT*CC];
__device__ __half  g_K [(size_t)BB*TK*CC];
__device__ __half  g_V [(size_t)BB*TK*CC];
__device__ __half  g_O [(size_t)BB*TT*CC];
__device__ uint32_t g_Wqt[(size_t)CC*CW];
__device__ uint32_t g_Wkt[(size_t)CC*CW];
__device__ uint32_t g_Wvt[(size_t)CC*CW];
__device__ uint32_t g_Wot[(size_t)CC*CW];

// ---------------------------------------------------------------------------
// helpers
// ---------------------------------------------------------------------------
__device__ __forceinline__ uint32_t packh2(float a, float b) {
    __half2 h = __floats2half2_rn(a, b);
    return *reinterpret_cast<uint32_t*>(&h);
}

// D += A(16x16) * B(16x8), fp16 inputs, fp32 accumulate
__device__ __forceinline__ void mma16(float* c, const uint32_t* a, const uint32_t* b) {
    asm volatile(
        "mma.sync.aligned.m16n8k16.row.col.f32.f16.f16.f32 "
        "{%0,%1,%2,%3}, {%4,%5,%6,%7}, {%8,%9}, {%0,%1,%2,%3};"
        : "+f"(c[0]), "+f"(c[1]), "+f"(c[2]), "+f"(c[3])
        : "r"(a[0]), "r"(a[1]), "r"(a[2]), "r"(a[3]), "r"(b[0]), "r"(b[1]));
}

__device__ __forceinline__ void cp16(uint32_t dst_smem, const void* src, bool pred) {
    int sz = pred ? 16 : 0;
    asm volatile("cp.async.ca.shared.global [%0], [%1], 16, %2;"
                 :: "r"(dst_smem), "l"(src), "r"(sz));
}
__device__ __forceinline__ void cp_commit() { asm volatile("cp.async.commit_group;"); }

// ---------------------------------------------------------------------------
// Weight conversion: fp32 [k][n] -> fp16 k-paired [n][k/2] words. One-shot.
// block (32,32), grid (CC/32, CC/32, 4). smem tile transpose.
// ---------------------------------------------------------------------------
__global__ void cvt_weights(const float* __restrict__ Wq, const float* __restrict__ Wk,
                            const float* __restrict__ Wv, const float* __restrict__ Wo)
{
    __shared__ float tile[32][33];
    const float* W = (blockIdx.z == 0) ? Wq : (blockIdx.z == 1) ? Wk
                   : (blockIdx.z == 2) ? Wv : Wo;
    uint32_t* out = (blockIdx.z == 0) ? g_Wqt : (blockIdx.z == 1) ? g_Wkt
                  : (blockIdx.z == 2) ? g_Wvt : g_Wot;
    int k0 = blockIdx.x * 32, n0 = blockIdx.y * 32;
    int tx = threadIdx.x, ty = threadIdx.y;
    tile[ty][tx] = W[(size_t)(k0 + ty)*CC + n0 + tx];
    __syncthreads();
    if (tx < 16)
        out[(size_t)(n0 + ty)*CW + (k0 >> 1) + tx] =
            packh2(tile[2*tx][ty], tile[2*tx + 1][ty]);
}

// ---------------------------------------------------------------------------
// Depthwise 3x3 conv (stride 1, SAME) + BN, q path. fp16 out.
// ---------------------------------------------------------------------------
__global__ void dwbn_q_kernel(const float* __restrict__ x,
                              const float* __restrict__ w,
                              const float* __restrict__ gamma,
                              const float* __restrict__ beta,
                              const float* __restrict__ mean,
                              const float* __restrict__ var,
                              __half* __restrict__ out)
{
    int c  = threadIdx.x;
    int sp = blockIdx.x;
    int b  = sp / TT;
    int t  = sp - b * TT;
    int y  = t / WW;
    int xw = t - y * WW;

    float acc = 0.f;
#pragma unroll
    for (int dy = 0; dy < 3; ++dy) {
        int yy = y + dy - 1;
        if (yy < 0 || yy >= HH) continue;
#pragma unroll
        for (int dx = 0; dx < 3; ++dx) {
            int xx = xw + dx - 1;
            if (xx < 0 || xx >= WW) continue;
            acc += x[((size_t)b*TT + yy*WW + xx)*CC + c] * w[(dy*3+dx)*CC + c];
        }
    }
    float sc = gamma[c] * rsqrtf(var[c] + EPSV);
    out[(size_t)sp*CC + c] = __float2half_rn(sc * (acc - mean[c]) + beta[c]);
}

// ---------------------------------------------------------------------------
// Depthwise 3x3 conv (stride 2, VALID) + BN, fused k+v. fp16 out.
// ---------------------------------------------------------------------------
__global__ void dwbn_kv_kernel(const float* __restrict__ x,
                               const float* __restrict__ wk,
                               const float* __restrict__ kg,
                               const float* __restrict__ kb,
                               const float* __restrict__ km,
                               const float* __restrict__ kvv,
                               const float* __restrict__ wv,
                               const float* __restrict__ vg,
                               const float* __restrict__ vb,
                               const float* __restrict__ vm,
                               const float* __restrict__ vvv,
                               __half* __restrict__ outk,
                               __half* __restrict__ outv)
{
    int c  = threadIdx.x;
    int sp = blockIdx.x;
    int b  = sp / TK;
    int t  = sp - b * TK;
    int y  = t / HK;
    int xw = t - y * HK;

    float ak = 0.f, av = 0.f;
#pragma unroll
    for (int dy = 0; dy < 3; ++dy) {
#pragma unroll
        for (int dx = 0; dx < 3; ++dx) {
            float xv = x[((size_t)b*TT + (2*y+dy)*WW + (2*xw+dx))*CC + c];
            ak += xv * wk[(dy*3+dx)*CC + c];
            av += xv * wv[(dy*3+dx)*CC + c];
        }
    }
    float sck = kg[c] * rsqrtf(kvv[c] + EPSV);
    float scv = vg[c] * rsqrtf(vvv[c] + EPSV);
    outk[(size_t)sp*CC + c] = __float2half_rn(sck * (ak - km[c]) + kb[c]);
    outv[(size_t)sp*CC + c] = __float2half_rn(scv * (av - vm[c]) + vb[c]);
}

// ---------------------------------------------------------------------------
// FP16 GEMM: C[M,384] = A[M,384] @ W (+bias). A fp16 row-major; W k-paired.
// 256 threads (8 warps, 2m x 4n), block 128x128, warp 64x32, BK=32 halves
// (16 words), cp.async double-buffered. Output: half2 (Ch) or fp32+bias (Cf).
// Strides AST=BST=20 words: bank = 20*g+tg ≡ 4g+tg mod 32, conflict-free.
// ---------------------------------------------------------------------------
#define GBM 128
#define GBN 128
#define BKW 16           // words per row per stage (= 32 halves)
#define AST 20
#define BST 20
#define NT  12           // 384/32

__global__ __launch_bounds__(256, 2)
void gemm_f16(const __half* __restrict__ A, const uint32_t* __restrict__ W2,
              const float* __restrict__ bias, __half* __restrict__ Ch,
              float* __restrict__ Cf, int M)
{
    __shared__ uint32_t As[2][GBM*AST];
    __shared__ uint32_t Bs[2][GBN*BST];

    int tid  = threadIdx.x;
    int warp = tid >> 5;
    int lane = tid & 31;
    int g    = lane >> 2;
    int tg   = lane & 3;
    int bm   = blockIdx.x * GBM;
    int bn   = blockIdx.y * GBN;
    int wm   = (warp >> 2) * 64;
    int wn   = (warp & 3) * 32;

    int l_r = tid >> 2;          // 0..63 (x2 -> 128 rows)
    int l_q = (tid & 3) * 4;     // word offset within stage row (0,4,8,12)

    uint32_t sA[2], sB[2];
    sA[0] = (uint32_t)__cvta_generic_to_shared(&As[0][0]);
    sA[1] = (uint32_t)__cvta_generic_to_shared(&As[1][0]);
    sB[0] = (uint32_t)__cvta_generic_to_shared(&Bs[0][0]);
    sB[1] = (uint32_t)__cvta_generic_to_shared(&Bs[1][0]);

    float acc[4][4][4];
#pragma unroll
    for (int mf = 0; mf < 4; ++mf)
#pragma unroll
        for (int nf = 0; nf < 4; ++nf)
#pragma unroll
            for (int c = 0; c < 4; ++c) acc[mf][nf][c] = 0.f;

    auto load_stage = [&](int t, int buf) {
#pragma unroll
        for (int i = 0; i < 2; ++i) {
            int r  = i*64 + l_r;
            int gr = bm + r;
            bool p = (gr < M);
            const __half* src = &A[(size_t)(p ? gr : 0)*CC + t*32 + l_q*2];
            cp16(sA[buf] + (uint32_t)(r*AST + l_q)*4u, src, p);
        }
#pragma unroll
        for (int i = 0; i < 2; ++i) {
            int n = i*64 + l_r;
            const uint32_t* src = &W2[(size_t)(bn + n)*CW + t*BKW + l_q];
            cp16(sB[buf] + (uint32_t)(n*BST + l_q)*4u, src, true);
        }
        cp_commit();
    };

    load_stage(0, 0);

    for (int t = 0; t < NT; ++t) {
        int buf = t & 1;
        if (t + 1 < NT) {
            load_stage(t + 1, buf ^ 1);
            asm volatile("cp.async.wait_group 1;");
        } else {
            asm volatile("cp.async.wait_group 0;");
        }
        __syncthreads();

        const uint32_t* Ab = As[buf];
        const uint32_t* Bb = Bs[buf];
#pragma unroll
        for (int s = 0; s < 2; ++s) {          // two k16 steps per stage
            int kw = s * 8;
            uint32_t af[4][4];
#pragma unroll
            for (int mf = 0; mf < 4; ++mf) {
                int rb = wm + mf*16;
                af[mf][0] = Ab[(rb + g    )*AST + kw + tg    ];
                af[mf][1] = Ab[(rb + g + 8)*AST + kw + tg    ];
                af[mf][2] = Ab[(rb + g    )*AST + kw + tg + 4];
                af[mf][3] = Ab[(rb + g + 8)*AST + kw + tg + 4];
            }
#pragma unroll
            for (int nf = 0; nf < 4; ++nf) {
                int nr = wn + nf*8 + g;
                uint32_t bf[2];
                bf[0] = Bb[nr*BST + kw + tg    ];
                bf[1] = Bb[nr*BST + kw + tg + 4];
#pragma unroll
                for (int mf = 0; mf < 4; ++mf)
                    mma16(acc[mf][nf], af[mf], bf);
            }
        }
        __syncthreads();
    }

    // Epilogue
#pragma unroll
    for (int mf = 0; mf < 4; ++mf) {
#pragma unroll
        for (int i = 0; i < 2; ++i) {
            int gr = bm + wm + mf*16 + g + i*8;
            if (gr >= M) continue;
#pragma unroll
            for (int nf = 0; nf < 4; ++nf) {
                int col = bn + wn + nf*8 + tg*2;
                if (Cf) {
                    float2 v;
                    v.x = acc[mf][nf][i*2 + 0] + bias[col];
                    v.y = acc[mf][nf][i*2 + 1] + bias[col+1];
                    *(float2*)&Cf[(size_t)gr*CC + col] = v;
                } else {
                    uint32_t w = packh2(acc[mf][nf][i*2 + 0], acc[mf][nf][i*2 + 1]);
                    *(uint32_t*)&Ch[(size_t)gr*CC + col] = w;
                }
            }
        }
    }
}

// ---------------------------------------------------------------------------
// FP16 attention: register-resident S/P, no shuffles (fp16 C->A relayout is
// a plain pack). 8 warps x 16 q-rows = 128 rows/block, grid (7, BB*NHEAD).
// smem: Ks[j][d/2] 176x36 words + Vs[d][j/2] 64x100 words = 49.75 KB.
// ---------------------------------------------------------------------------
#define JP    176
#define NKC   22     // JP/8 n-blocks for S
#define KST   36     // 32 words + 4 pad  (36 ≡ 4 mod 32)
#define VST   100    // 88 words + 12 pad (100 ≡ 4 mod 32)

__global__ __launch_bounds__(256, 2)
void attn_f16(const __half* __restrict__ Q, const __half* __restrict__ K,
              const __half* __restrict__ V, __half* __restrict__ O)
{
    extern __shared__ uint32_t sm[];
    uint32_t* Ks = sm;               // [j][dw] 176*36
    uint32_t* Vs = sm + JP*KST;      // [d][jw] 64*100

    int tid  = threadIdx.x;
    int warp = tid >> 5;
    int lane = tid & 31;
    int g    = lane >> 2;
    int tg   = lane & 3;
    int bh   = blockIdx.y;
    int b    = bh / NHEAD;
    int h    = bh - b * NHEAD;
    int row0 = blockIdx.x * 128;
    const float scale = rsqrtf((float)CC);

    // Ks: K rows as natural d-pairs (coalesced word loads), zero-pad j>=TK
    const uint32_t* Kw = (const uint32_t*)K;
    for (int idx = tid; idx < JP*32; idx += 256) {
        int j = idx >> 5, dw = idx & 31;
        Ks[j*KST + dw] = (j < TK) ? Kw[((size_t)b*TK + j)*CW + h*32 + dw] : 0u;
    }
    // Vs: transposed j-pairs per d (two u16 gathers per word)
    for (int idx = tid; idx < 64*88; idx += 256) {
        int jw = idx >> 6, d = idx & 63;
        int j0 = 2*jw, j1 = 2*jw + 1;
        float v0 = (j0 < TK) ? __half2float(V[((size_t)b*TK + j0)*CC + h*DD + d]) : 0.f;
        float v1 = (j1 < TK) ? __half2float(V[((size_t)b*TK + j1)*CC + h*DD + d]) : 0.f;
        Vs[d*VST + jw] = packh2(v0, v1);
    }
    __syncthreads();

    // ---- S = Q K^T : each warp 16 rows x 176 cols ----
    int r0 = row0 + warp * 16;
    const uint32_t* Qw = (const uint32_t*)(Q) + (size_t)b*TT*CW + h*32;

    float p[NKC][4];
#pragma unroll
    for (int ni = 0; ni < NKC; ++ni)
#pragma unroll
        for (int c = 0; c < 4; ++c) p[ni][c] = 0.f;

#pragma unroll
    for (int kc = 0; kc < 4; ++kc) {        // d = 64 -> 4 k16 steps
        int kw = kc * 8;
        int ra = r0 + g, rb = r0 + g + 8;
        uint32_t af[4];
        af[0] = (ra < TT) ? Qw[(size_t)ra*CW + kw + tg    ] : 0u;
        af[1] = (rb < TT) ? Qw[(size_t)rb*CW + kw + tg    ] : 0u;
        af[2] = (ra < TT) ? Qw[(size_t)ra*CW + kw + tg + 4] : 0u;
        af[3] = (rb < TT) ? Qw[(size_t)rb*CW + kw + tg + 4] : 0u;
#pragma unroll
        for (int ni = 0; ni < NKC; ++ni) {
            uint32_t bf[2];
            bf[0] = Ks[(ni*8 + g)*KST + kw + tg    ];
            bf[1] = Ks[(ni*8 + g)*KST + kw + tg + 4];
            mma16(p[ni], af, bf);
        }
    }

    // ---- scale + mask + softmax in registers ----
    float m0 = -1e30f, m1 = -1e30f;
#pragma unroll
    for (int ni = 0; ni < NKC; ++ni) {
        int c0 = ni*8 + 2*tg, c1 = c0 + 1;
        p[ni][0] = (c0 < TK) ? p[ni][0]*scale : -1e30f;
        p[ni][1] = (c1 < TK) ? p[ni][1]*scale : -1e30f;
        p[ni][2] = (c0 < TK) ? p[ni][2]*scale : -1e30f;
        p[ni][3] = (c1 < TK) ? p[ni][3]*scale : -1e30f;
        m0 = fmaxf(m0, fmaxf(p[ni][0], p[ni][1]));
        m1 = fmaxf(m1, fmaxf(p[ni][2], p[ni][3]));
    }
    m0 = fmaxf(m0, __shfl_xor_sync(~0u, m0, 1));
    m0 = fmaxf(m0, __shfl_xor_sync(~0u, m0, 2));
    m1 = fmaxf(m1, __shfl_xor_sync(~0u, m1, 1));
    m1 = fmaxf(m1, __shfl_xor_sync(~0u, m1, 2));

    float s0 = 0.f, s1 = 0.f;
#pragma unroll
    for (int ni = 0; ni < NKC; ++ni) {
        p[ni][0] = __expf(p[ni][0] - m0);
        p[ni][1] = __expf(p[ni][1] - m0);
        p[ni][2] = __expf(p[ni][2] - m1);
        p[ni][3] = __expf(p[ni][3] - m1);
        s0 += p[ni][0] + p[ni][1];
        s1 += p[ni][2] + p[ni][3];
    }
    s0 += __shfl_xor_sync(~0u, s0, 1);
    s0 += __shfl_xor_sync(~0u, s0, 2);
    s1 += __shfl_xor_sync(~0u, s1, 1);
    s1 += __shfl_xor_sync(~0u, s1, 2);
    float i0 = 1.f / s0, i1 = 1.f / s1;

    // pack P directly into fp16 A-fragments (C cols 2tg,2tg+1 = A k-pairs)
    uint32_t p2[2*NKC];
#pragma unroll
    for (int ni = 0; ni < NKC; ++ni) {
        p2[2*ni    ] = packh2(p[ni][0]*i0, p[ni][1]*i0);
        p2[2*ni + 1] = packh2(p[ni][2]*i1, p[ni][3]*i1);
    }

    // ---- O = P V : 11 k16 steps over j, 8 n-blocks over d ----
    float oacc[8][4];
#pragma unroll
    for (int nf = 0; nf < 8; ++nf)
#pragma unroll
        for (int c = 0; c < 4; ++c) oacc[nf][c] = 0.f;

#pragma unroll
    for (int kc = 0; kc < 11; ++kc) {
        uint32_t af[4];
        af[0] = p2[4*kc    ];
        af[1] = p2[4*kc + 1];
        af[2] = p2[4*kc + 2];
        af[3] = p2[4*kc + 3];
        int jw = kc * 8;
#pragma unroll
        for (int nf = 0; nf < 8; ++nf) {
            uint32_t bf[2];
            bf[0] = Vs[(nf*8 + g)*VST + jw + tg    ];
            bf[1] = Vs[(nf*8 + g)*VST + jw + tg + 4];
            mma16(oacc[nf], af, bf);
        }
    }

#pragma unroll
    for (int nf = 0; nf < 8; ++nf) {
#pragma unroll
        for (int i = 0; i < 2; ++i) {
            int gr = r0 + g + i*8;
            if (gr >= TT) continue;
            int col = h*DD + nf*8 + tg*2;
            uint32_t w = packh2(oacc[nf][i*2 + 0], oacc[nf][i*2 + 1]);
            *(uint32_t*)&O[((size_t)b*TT + gr)*CC + col] = w;
        }
    }
}

static const int ATTN_SMEM = (JP*KST + 64*VST) * (int)sizeof(uint32_t);  // 50944

extern "C" void kernel_launch(void* const* d_in, const int* in_sizes, int n_in,
                              void* d_out, int out_size)
{
    (void)in_sizes; (void)n_in; (void)out_size;
    const float* x   = (const float*)d_in[0];
    const float* wq  = (const float*)d_in[1];
    const float* qg  = (const float*)d_in[2];
    const float* qb  = (const float*)d_in[3];
    const float* qm  = (const float*)d_in[4];
    const float* qv  = (const float*)d_in[5];
    const float* wk  = (const float*)d_in[6];
    const float* kg  = (const float*)d_in[7];
    const float* kb  = (const float*)d_in[8];
    const float* km  = (const float*)d_in[9];
    const float* kv_ = (const float*)d_in[10];
    const float* wv  = (const float*)d_in[11];
    const float* vg  = (const float*)d_in[12];
    const float* vb  = (const float*)d_in[13];
    const float* vm  = (const float*)d_in[14];
    const float* vv_ = (const float*)d_in[15];
    const float* Wq  = (const float*)d_in[16];
    const float* Wk  = (const float*)d_in[17];
    const float* Wv  = (const float*)d_in[18];
    const float* Wo  = (const float*)d_in[19];
    const float* bo  = (const float*)d_in[20];
    float* out = (float*)d_out;

    __half *qc, *kc, *vc, *Qp, *Kp, *Vp, *Op;
    uint32_t *Wqt, *Wkt, *Wvt, *Wot;
    cudaGetSymbolAddress((void**)&qc, g_qc);
    cudaGetSymbolAddress((void**)&kc, g_kc);
    cudaGetSymbolAddress((void**)&vc, g_vc);
    cudaGetSymbolAddress((void**)&Qp, g_Q);
    cudaGetSymbolAddress((void**)&Kp, g_K);
    cudaGetSymbolAddress((void**)&Vp, g_V);
    cudaGetSymbolAddress((void**)&Op, g_O);
    cudaGetSymbolAddress((void**)&Wqt, g_Wqt);
    cudaGetSymbolAddress((void**)&Wkt, g_Wkt);
    cudaGetSymbolAddress((void**)&Wvt, g_Wvt);
    cudaGetSymbolAddress((void**)&Wot, g_Wot);

    // 0. weight conversion (one-shot per launch, tiny)
    dim3 wg(CC/32, CC/32, 4);
    cvt_weights<<<wg, dim3(32,32)>>>(Wq, Wk, Wv, Wo);

    // 1. conv projections (fp16 out)
    dwbn_q_kernel <<<BB*TT, CC>>>(x, wq, qg, qb, qm, qv, qc);
    dwbn_kv_kernel<<<BB*TK, CC>>>(x, wk, kg, kb, km, kv_, wv, vg, vb, vm, vv_, kc, vc);

    // 2. dense projections (fp16 tensor cores)
    const int MQ = BB*TT;   // 50176
    const int MK = BB*TK;   // 10816
    dim3 gq((MQ + GBM - 1)/GBM, CC/GBN);   // 392 x 3
    dim3 gk((MK + GBM - 1)/GBM, CC/GBN);   // 85 x 3
    gemm_f16<<<gq, 256>>>(qc, Wqt, nullptr, Qp, nullptr, MQ);
    gemm_f16<<<gk, 256>>>(kc, Wkt, nullptr, Kp, nullptr, MK);
    gemm_f16<<<gk, 256>>>(vc, Wvt, nullptr, Vp, nullptr, MK);

    // 3. attention
    cudaFuncSetAttribute(attn_f16, cudaFuncAttributeMaxDynamicSharedMemorySize, ATTN_SMEM);
    dim3 ga((TT + 127)/128, BB*NHEAD);   // 7 x 384
    attn_f16<<<ga, 256, ATTN_SMEM>>>(Qp, Kp, Vp, Op);

    // 4. output projection (+bias, fp32 out)
    gemm_f16<<<gq, 256>>>(Op, Wot, bo, nullptr, out, MQ);
}

// round 7
// speedup vs baseline: 1.6058x; 1.1950x over previous
#include <cuda_runtime.h>
#include <cuda_fp16.h>
#include <math.h>
#include <stdint.h>

// Problem constants
#define BB   64
#define HH   28
#define WW   28
#define CC   384
#define TT   784      // HH*WW
#define HK   13       // (28-3)/2+1
#define TK   169      // 13*13
#define NHEAD 6
#define DD   64
#define EPSV 1e-3f
#define CW   (CC/2)   // 192 half2-words per row

// Scratch (device globals). Activations fp16; weights k-paired [n][k/2].
__device__ __half  g_qc[(size_t)BB*TT*CC];
__device__ __half  g_kc[(size_t)BB*TK*CC];
__device__ __half  g_vc[(size_t)BB*TK*CC];
__device__ __half  g_Q [(size_t)BB*TT*CC];
__device__ __half  g_K [(size_t)BB*TK*CC];
__device__ __half  g_V [(size_t)BB*TK*CC];
__device__ __half  g_O [(size_t)BB*TT*CC];
__device__ uint32_t g_Wqt[(size_t)CC*CW];
__device__ uint32_t g_Wkt[(size_t)CC*CW];
__device__ uint32_t g_Wvt[(size_t)CC*CW];
__device__ uint32_t g_Wot[(size_t)CC*CW];

// ---------------------------------------------------------------------------
// helpers
// ---------------------------------------------------------------------------
__device__ __forceinline__ uint32_t packh2(float a, float b) {
    __half2 h = __floats2half2_rn(a, b);
    return *reinterpret_cast<uint32_t*>(&h);
}

__device__ __forceinline__ void mma16(float* c, const uint32_t* a, const uint32_t* b) {
    asm volatile(
        "mma.sync.aligned.m16n8k16.row.col.f32.f16.f16.f32 "
        "{%0,%1,%2,%3}, {%4,%5,%6,%7}, {%8,%9}, {%0,%1,%2,%3};"
        : "+f"(c[0]), "+f"(c[1]), "+f"(c[2]), "+f"(c[3])
        : "r"(a[0]), "r"(a[1]), "r"(a[2]), "r"(a[3]), "r"(b[0]), "r"(b[1]));
}

__device__ __forceinline__ void ldsm_x4(uint32_t* r, uint32_t addr) {
    asm volatile("ldmatrix.sync.aligned.m8n8.x4.shared.b16 {%0,%1,%2,%3}, [%4];"
                 : "=r"(r[0]), "=r"(r[1]), "=r"(r[2]), "=r"(r[3]) : "r"(addr));
}
__device__ __forceinline__ void ldsm_x2(uint32_t* r, uint32_t addr) {
    asm volatile("ldmatrix.sync.aligned.m8n8.x2.shared.b16 {%0,%1}, [%2];"
                 : "=r"(r[0]), "=r"(r[1]) : "r"(addr));
}
__device__ __forceinline__ void ldsm_x2t(uint32_t* r, uint32_t addr) {
    asm volatile("ldmatrix.sync.aligned.m8n8.x2.trans.shared.b16 {%0,%1}, [%2];"
                 : "=r"(r[0]), "=r"(r[1]) : "r"(addr));
}

__device__ __forceinline__ void cp16(uint32_t dst_smem, const void* src, bool pred) {
    int sz = pred ? 16 : 0;   // sz=0 -> 16B zero-fill
    asm volatile("cp.async.ca.shared.global [%0], [%1], 16, %2;"
                 :: "r"(dst_smem), "l"(src), "r"(sz));
}
__device__ __forceinline__ void cp_commit() { asm volatile("cp.async.commit_group;"); }

// ---------------------------------------------------------------------------
// Weight conversion: fp32 [k][n] -> fp16 k-paired [n][k/2] words. One-shot.
// ---------------------------------------------------------------------------
__global__ void cvt_weights(const float* __restrict__ Wq, const float* __restrict__ Wk,
                            const float* __restrict__ Wv, const float* __restrict__ Wo)
{
    __shared__ float tile[32][33];
    const float* W = (blockIdx.z == 0) ? Wq : (blockIdx.z == 1) ? Wk
                   : (blockIdx.z == 2) ? Wv : Wo;
    uint32_t* out = (blockIdx.z == 0) ? g_Wqt : (blockIdx.z == 1) ? g_Wkt
                  : (blockIdx.z == 2) ? g_Wvt : g_Wot;
    int k0 = blockIdx.x * 32, n0 = blockIdx.y * 32;
    int tx = threadIdx.x, ty = threadIdx.y;
    tile[ty][tx] = W[(size_t)(k0 + ty)*CC + n0 + tx];
    __syncthreads();
    if (tx < 16)
        out[(size_t)(n0 + ty)*CW + (k0 >> 1) + tx] =
            packh2(tile[2*tx][ty], tile[2*tx + 1][ty]);
}

// ---------------------------------------------------------------------------
// Depthwise 3x3 conv + BN kernels (fp16 out)
// ---------------------------------------------------------------------------
__global__ void dwbn_q_kernel(const float* __restrict__ x,
                              const float* __restrict__ w,
                              const float* __restrict__ gamma,
                              const float* __restrict__ beta,
                              const float* __restrict__ mean,
                              const float* __restrict__ var,
                              __half* __restrict__ out)
{
    int c  = threadIdx.x;
    int sp = blockIdx.x;
    int b  = sp / TT;
    int t  = sp - b * TT;
    int y  = t / WW;
    int xw = t - y * WW;

    float acc = 0.f;
#pragma unroll
    for (int dy = 0; dy < 3; ++dy) {
        int yy = y + dy - 1;
        if (yy < 0 || yy >= HH) continue;
#pragma unroll
        for (int dx = 0; dx < 3; ++dx) {
            int xx = xw + dx - 1;
            if (xx < 0 || xx >= WW) continue;
            acc += x[((size_t)b*TT + yy*WW + xx)*CC + c] * w[(dy*3+dx)*CC + c];
        }
    }
    float sc = gamma[c] * rsqrtf(var[c] + EPSV);
    out[(size_t)sp*CC + c] = __float2half_rn(sc * (acc - mean[c]) + beta[c]);
}

__global__ void dwbn_kv_kernel(const float* __restrict__ x,
                               const float* __restrict__ wk,
                               const float* __restrict__ kg,
                               const float* __restrict__ kb,
                               const float* __restrict__ km,
                               const float* __restrict__ kvv,
                               const float* __restrict__ wv,
                               const float* __restrict__ vg,
                               const float* __restrict__ vb,
                               const float* __restrict__ vm,
                               const float* __restrict__ vvv,
                               __half* __restrict__ outk,
                               __half* __restrict__ outv)
{
    int c  = threadIdx.x;
    int sp = blockIdx.x;
    int b  = sp / TK;
    int t  = sp - b * TK;
    int y  = t / HK;
    int xw = t - y * HK;

    float ak = 0.f, av = 0.f;
#pragma unroll
    for (int dy = 0; dy < 3; ++dy) {
#pragma unroll
        for (int dx = 0; dx < 3; ++dx) {
            float xv = x[((size_t)b*TT + (2*y+dy)*WW + (2*xw+dx))*CC + c];
            ak += xv * wk[(dy*3+dx)*CC + c];
            av += xv * wv[(dy*3+dx)*CC + c];
        }
    }
    float sck = kg[c] * rsqrtf(kvv[c] + EPSV);
    float scv = vg[c] * rsqrtf(vvv[c] + EPSV);
    outk[(size_t)sp*CC + c] = __float2half_rn(sck * (ak - km[c]) + kb[c]);
    outv[(size_t)sp*CC + c] = __float2half_rn(scv * (av - vm[c]) + vb[c]);
}

// ---------------------------------------------------------------------------
// FP16 GEMM v4 (ldmatrix): C[M,384] = A @ W (+bias).
// 256 threads (8 warps 2m x 4n), block 128x128, warp 64x32, BK=32 halves,
// cp.async double-buffered, ldmatrix fragment loads.
// ---------------------------------------------------------------------------
#define GBM 128
#define GBN 128
#define AST 20
#define BST 20
#define NT  12           // 384/32

__global__ __launch_bounds__(256, 2)
void gemm_f16(const __half* __restrict__ A, const uint32_t* __restrict__ W2,
              const float* __restrict__ bias, __half* __restrict__ Ch,
              float* __restrict__ Cf, int M)
{
    __shared__ uint32_t As[2][GBM*AST];
    __shared__ uint32_t Bs[2][GBN*BST];

    int tid  = threadIdx.x;
    int warp = tid >> 5;
    int lane = tid & 31;
    int g    = lane >> 2;
    int tg   = lane & 3;
    int bm   = blockIdx.x * GBM;
    int bn   = blockIdx.y * GBN;
    int wm   = (warp >> 2) * 64;
    int wn   = (warp & 3) * 32;

    int l_r = tid >> 2;
    int l_q = (tid & 3) * 4;

    // ldmatrix lane offsets
    int a_row = (lane & 7) | (lane & 8);   // 0..15
    int a_kof = (lane >> 4) << 2;          // 0 or 4
    int b_row = lane & 7;
    int b_kof = (lane & 8) ? 4 : 0;

    uint32_t sA[2], sB[2];
    sA[0] = (uint32_t)__cvta_generic_to_shared(&As[0][0]);
    sA[1] = (uint32_t)__cvta_generic_to_shared(&As[1][0]);
    sB[0] = (uint32_t)__cvta_generic_to_shared(&Bs[0][0]);
    sB[1] = (uint32_t)__cvta_generic_to_shared(&Bs[1][0]);

    float acc[4][4][4];
#pragma unroll
    for (int mf = 0; mf < 4; ++mf)
#pragma unroll
        for (int nf = 0; nf < 4; ++nf)
#pragma unroll
            for (int c = 0; c < 4; ++c) acc[mf][nf][c] = 0.f;

    auto load_stage = [&](int t, int buf) {
#pragma unroll
        for (int i = 0; i < 2; ++i) {
            int r  = i*64 + l_r;
            int gr = bm + r;
            bool p = (gr < M);
            const __half* src = &A[(size_t)(p ? gr : 0)*CC + t*32 + l_q*2];
            cp16(sA[buf] + (uint32_t)(r*AST + l_q)*4u, src, p);
        }
#pragma unroll
        for (int i = 0; i < 2; ++i) {
            int n = i*64 + l_r;
            const uint32_t* src = &W2[(size_t)(bn + n)*CW + t*16 + l_q];
            cp16(sB[buf] + (uint32_t)(n*BST + l_q)*4u, src, true);
        }
        cp_commit();
    };

    load_stage(0, 0);

    for (int t = 0; t < NT; ++t) {
        int buf = t & 1;
        if (t + 1 < NT) {
            load_stage(t + 1, buf ^ 1);
            asm volatile("cp.async.wait_group 1;");
        } else {
            asm volatile("cp.async.wait_group 0;");
        }
        __syncthreads();

        uint32_t ab = sA[buf];
        uint32_t bb = sB[buf];
#pragma unroll
        for (int s = 0; s < 2; ++s) {
            int kw = s * 8;
            uint32_t af[4][4], bf[4][2];
#pragma unroll
            for (int mf = 0; mf < 4; ++mf)
                ldsm_x4(af[mf], ab + 4u*((wm + mf*16 + a_row)*AST + kw + a_kof));
#pragma unroll
            for (int nf = 0; nf < 4; ++nf)
                ldsm_x2(bf[nf], bb + 4u*((wn + nf*8 + b_row)*BST + kw + b_kof));
#pragma unroll
            for (int nf = 0; nf < 4; ++nf)
#pragma unroll
                for (int mf = 0; mf < 4; ++mf)
                    mma16(acc[mf][nf], af[mf], bf[nf]);
        }
        __syncthreads();
    }

    // Epilogue
#pragma unroll
    for (int mf = 0; mf < 4; ++mf) {
#pragma unroll
        for (int i = 0; i < 2; ++i) {
            int gr = bm + wm + mf*16 + g + i*8;
            if (gr >= M) continue;
#pragma unroll
            for (int nf = 0; nf < 4; ++nf) {
                int col = bn + wn + nf*8 + tg*2;
                if (Cf) {
                    float2 v;
                    v.x = acc[mf][nf][i*2 + 0] + bias[col];
                    v.y = acc[mf][nf][i*2 + 1] + bias[col+1];
                    *(float2*)&Cf[(size_t)gr*CC + col] = v;
                } else {
                    uint32_t w = packh2(acc[mf][nf][i*2 + 0], acc[mf][nf][i*2 + 1]);
                    *(uint32_t*)&Ch[(size_t)gr*CC + col] = w;
                }
            }
        }
    }
}

// ---------------------------------------------------------------------------
// FP16 attention v5: cp.async staging for Q/K/V, ldmatrix fragments,
// register-resident S/P. 8 warps x 16 q-rows = 128 rows/block.
// smem: Qs 128x36 + Ks 176x36 + Vs 176x36 words = 67.5 KB.
// K: [j][dw] (non-trans B-frags). V: [j][dw] + ldmatrix.trans for PV B-frags.
// ---------------------------------------------------------------------------
#define JP   176
#define NKC  22      // JP/8
#define QST  36
#define KST  36
#define VST  36

__global__ __launch_bounds__(256, 2)
void attn_f16(const __half* __restrict__ Q, const __half* __restrict__ K,
              const __half* __restrict__ V, __half* __restrict__ O)
{
    extern __shared__ uint32_t sm[];
    uint32_t* Qs = sm;                     // [r][dw] 128*36
    uint32_t* Ks = Qs + 128*QST;           // [j][dw] 176*36
    uint32_t* Vs = Ks + JP*KST;            // [j][dw] 176*36

    int tid  = threadIdx.x;
    int warp = tid >> 5;
    int lane = tid & 31;
    int g    = lane >> 2;
    int tg   = lane & 3;
    int bh   = blockIdx.y;
    int b    = bh / NHEAD;
    int h    = bh - b * NHEAD;
    int row0 = blockIdx.x * 128;
    const float scale = rsqrtf((float)CC);

    int a_row = (lane & 7) | (lane & 8);
    int a_kof = (lane >> 4) << 2;
    int b_row = lane & 7;
    int b_kof = (lane & 8) ? 4 : 0;

    uint32_t qb = (uint32_t)__cvta_generic_to_shared(Qs);
    uint32_t kb = (uint32_t)__cvta_generic_to_shared(Ks);
    uint32_t vb = (uint32_t)__cvta_generic_to_shared(Vs);

    const uint32_t* Qw = (const uint32_t*)Q + (size_t)b*TT*CW + h*32;
    const uint32_t* Kw = (const uint32_t*)K + (size_t)b*TK*CW + h*32;
    const uint32_t* Vw = (const uint32_t*)V + (size_t)b*TK*CW + h*32;

    // Stage Q (128 rows x 32 words), zero-fill rows >= TT
    for (int idx = tid; idx < 128*8; idx += 256) {
        int r = idx >> 3, c4 = (idx & 7) * 4;
        int gr = row0 + r;
        bool p = (gr < TT);
        cp16(qb + 4u*(r*QST + c4), Qw + (size_t)(p ? gr : 0)*CW + c4, p);
    }
    // Stage K and V (176 rows x 32 words), zero-fill j >= TK
    for (int idx = tid; idx < JP*8; idx += 256) {
        int j = idx >> 3, c4 = (idx & 7) * 4;
        bool p = (j < TK);
        int js = p ? j : 0;
        cp16(kb + 4u*(j*KST + c4), Kw + (size_t)js*CW + c4, p);
        cp16(vb + 4u*(j*VST + c4), Vw + (size_t)js*CW + c4, p);
    }
    cp_commit();
    asm volatile("cp.async.wait_group 0;");
    __syncthreads();

    // ---- S = Q K^T : each warp 16 rows x 176 cols ----
    int r0 = row0 + warp * 16;

    float p[NKC][4];
#pragma unroll
    for (int ni = 0; ni < NKC; ++ni)
#pragma unroll
        for (int c = 0; c < 4; ++c) p[ni][c] = 0.f;

#pragma unroll
    for (int kc = 0; kc < 4; ++kc) {       // d = 64 halves -> 4 k16 steps
        int kw = kc * 8;
        uint32_t af[4];
        ldsm_x4(af, qb + 4u*((warp*16 + a_row)*QST + kw + a_kof));
#pragma unroll
        for (int ni = 0; ni < NKC; ++ni) {
            uint32_t bf[2];
            ldsm_x2(bf, kb + 4u*((ni*8 + b_row)*KST + kw + b_kof));
            mma16(p[ni], af, bf);
        }
    }

    // ---- scale + mask + softmax in registers ----
    float m0 = -1e30f, m1 = -1e30f;
#pragma unroll
    for (int ni = 0; ni < NKC; ++ni) {
        int c0 = ni*8 + 2*tg, c1 = c0 + 1;
        p[ni][0] = (c0 < TK) ? p[ni][0]*scale : -1e30f;
        p[ni][1] = (c1 < TK) ? p[ni][1]*scale : -1e30f;
        p[ni][2] = (c0 < TK) ? p[ni][2]*scale : -1e30f;
        p[ni][3] = (c1 < TK) ? p[ni][3]*scale : -1e30f;
        m0 = fmaxf(m0, fmaxf(p[ni][0], p[ni][1]));
        m1 = fmaxf(m1, fmaxf(p[ni][2], p[ni][3]));
    }
    m0 = fmaxf(m0, __shfl_xor_sync(~0u, m0, 1));
    m0 = fmaxf(m0, __shfl_xor_sync(~0u, m0, 2));
    m1 = fmaxf(m1, __shfl_xor_sync(~0u, m1, 1));
    m1 = fmaxf(m1, __shfl_xor_sync(~0u, m1, 2));

    float s0 = 0.f, s1 = 0.f;
#pragma unroll
    for (int ni = 0; ni < NKC; ++ni) {
        p[ni][0] = __expf(p[ni][0] - m0);
        p[ni][1] = __expf(p[ni][1] - m0);
        p[ni][2] = __expf(p[ni][2] - m1);
        p[ni][3] = __expf(p[ni][3] - m1);
        s0 += p[ni][0] + p[ni][1];
        s1 += p[ni][2] + p[ni][3];
    }
    s0 += __shfl_xor_sync(~0u, s0, 1);
    s0 += __shfl_xor_sync(~0u, s0, 2);
    s1 += __shfl_xor_sync(~0u, s1, 1);
    s1 += __shfl_xor_sync(~0u, s1, 2);
    float i0 = 1.f / s0, i1 = 1.f / s1;

    // pack P into fp16 A-fragments
    uint32_t p2[2*NKC];
#pragma unroll
    for (int ni = 0; ni < NKC; ++ni) {
        p2[2*ni    ] = packh2(p[ni][0]*i0, p[ni][1]*i0);
        p2[2*ni + 1] = packh2(p[ni][2]*i1, p[ni][3]*i1);
    }

    // ---- O = P V : 11 k16 steps (j), 8 n-blocks (d), V-frags via trans ----
    float oacc[8][4];
#pragma unroll
    for (int nf = 0; nf < 8; ++nf)
#pragma unroll
        for (int c = 0; c < 4; ++c) oacc[nf][c] = 0.f;

#pragma unroll
    for (int kc = 0; kc < 11; ++kc) {
        uint32_t af[4];
        af[0] = p2[4*kc    ];
        af[1] = p2[4*kc + 1];
        af[2] = p2[4*kc + 2];
        af[3] = p2[4*kc + 3];
        int jr = kc * 16;
#pragma unroll
        for (int nf = 0; nf < 8; ++nf) {
            uint32_t bf[2];
            ldsm_x2t(bf, vb + 4u*((jr + a_row)*VST + nf*4));
            mma16(oacc[nf], af, bf);
        }
    }

#pragma unroll
    for (int nf = 0; nf < 8; ++nf) {
#pragma unroll
        for (int i = 0; i < 2; ++i) {
            int gr = r0 + g + i*8;
            if (gr >= TT) continue;
            int col = h*DD + nf*8 + tg*2;
            uint32_t w = packh2(oacc[nf][i*2 + 0], oacc[nf][i*2 + 1]);
            *(uint32_t*)&O[((size_t)b*TT + gr)*CC + col] = w;
        }
    }
}

static const int ATTN_SMEM = (128*QST + JP*KST + JP*VST) * (int)sizeof(uint32_t); // 69120

extern "C" void kernel_launch(void* const* d_in, const int* in_sizes, int n_in,
                              void* d_out, int out_size)
{
    (void)in_sizes; (void)n_in; (void)out_size;
    const float* x   = (const float*)d_in[0];
    const float* wq  = (const float*)d_in[1];
    const float* qg  = (const float*)d_in[2];
    const float* qb  = (const float*)d_in[3];
    const float* qm  = (const float*)d_in[4];
    const float* qv  = (const float*)d_in[5];
    const float* wk  = (const float*)d_in[6];
    const float* kg  = (const float*)d_in[7];
    const float* kb  = (const float*)d_in[8];
    const float* km  = (const float*)d_in[9];
    const float* kv_ = (const float*)d_in[10];
    const float* wv  = (const float*)d_in[11];
    const float* vg  = (const float*)d_in[12];
    const float* vb  = (const float*)d_in[13];
    const float* vm  = (const float*)d_in[14];
    const float* vv_ = (const float*)d_in[15];
    const float* Wq  = (const float*)d_in[16];
    const float* Wk  = (const float*)d_in[17];
    const float* Wv  = (const float*)d_in[18];
    const float* Wo  = (const float*)d_in[19];
    const float* bo  = (const float*)d_in[20];
    float* out = (float*)d_out;

    __half *qc, *kc, *vc, *Qp, *Kp, *Vp, *Op;
    uint32_t *Wqt, *Wkt, *Wvt, *Wot;
    cudaGetSymbolAddress((void**)&qc, g_qc);
    cudaGetSymbolAddress((void**)&kc, g_kc);
    cudaGetSymbolAddress((void**)&vc, g_vc);
    cudaGetSymbolAddress((void**)&Qp, g_Q);
    cudaGetSymbolAddress((void**)&Kp, g_K);
    cudaGetSymbolAddress((void**)&Vp, g_V);
    cudaGetSymbolAddress((void**)&Op, g_O);
    cudaGetSymbolAddress((void**)&Wqt, g_Wqt);
    cudaGetSymbolAddress((void**)&Wkt, g_Wkt);
    cudaGetSymbolAddress((void**)&Wvt, g_Wvt);
    cudaGetSymbolAddress((void**)&Wot, g_Wot);

    // 0. weight conversion
    dim3 wg(CC/32, CC/32, 4);
    cvt_weights<<<wg, dim3(32,32)>>>(Wq, Wk, Wv, Wo);

    // 1. conv projections
    dwbn_q_kernel <<<BB*TT, CC>>>(x, wq, qg, qb, qm, qv, qc);
    dwbn_kv_kernel<<<BB*TK, CC>>>(x, wk, kg, kb, km, kv_, wv, vg, vb, vm, vv_, kc, vc);

    // 2. dense projections
    const int MQ = BB*TT;   // 50176
    const int MK = BB*TK;   // 10816
    dim3 gq((MQ + GBM - 1)/GBM, CC/GBN);   // 392 x 3
    dim3 gk((MK + GBM - 1)/GBM, CC/GBN);   // 85 x 3
    gemm_f16<<<gq, 256>>>(qc, Wqt, nullptr, Qp, nullptr, MQ);
    gemm_f16<<<gk, 256>>>(kc, Wkt, nullptr, Kp, nullptr, MK);
    gemm_f16<<<gk, 256>>>(vc, Wvt, nullptr, Vp, nullptr, MK);

    // 3. attention
    cudaFuncSetAttribute(attn_f16, cudaFuncAttributeMaxDynamicSharedMemorySize, ATTN_SMEM);
    dim3 ga((TT + 127)/128, BB*NHEAD);   // 7 x 384
    attn_f16<<<ga, 256, ATTN_SMEM>>>(Qp, Kp, Vp, Op);

    // 4. output projection (+bias, fp32 out)
    gemm_f16<<<gq, 256>>>(Op, Wot, bo, nullptr, out, MQ);
}

// round 9
// speedup vs baseline: 2.0721x; 1.2904x over previous
#include <cuda_runtime.h>
#include <cuda_fp16.h>
#include <math.h>
#include <stdint.h>

// Problem constants
#define BB   64
#define HH   28
#define WW   28
#define CC   384
#define TT   784      // HH*WW
#define HK   13       // (28-3)/2+1
#define TK   169      // 13*13
#define NHEAD 6
#define DD   64
#define EPSV 1e-3f
#define CW   (CC/2)   // 192 half2-words per row

// Scratch (device globals). Activations fp16; weights k-paired [n][k/2].
__device__ __half  g_qc[(size_t)BB*TT*CC];
__device__ __half  g_kc[(size_t)BB*TK*CC];
__device__ __half  g_vc[(size_t)BB*TK*CC];
__device__ __half  g_Q [(size_t)BB*TT*CC];
__device__ __half  g_K [(size_t)BB*TK*CC];
__device__ __half  g_V [(size_t)BB*TK*CC];
__device__ __half  g_O [(size_t)BB*TT*CC];
__device__ uint32_t g_Wqt[(size_t)CC*CW];
__device__ uint32_t g_Wkt[(size_t)CC*CW];
__device__ uint32_t g_Wvt[(size_t)CC*CW];
__device__ uint32_t g_Wot[(size_t)CC*CW];

// ---------------------------------------------------------------------------
// helpers
// ---------------------------------------------------------------------------
__device__ __forceinline__ uint32_t packh2(float a, float b) {
    __half2 h = __floats2half2_rn(a, b);
    return *reinterpret_cast<uint32_t*>(&h);
}

__device__ __forceinline__ void mma16(float* c, const uint32_t* a, const uint32_t* b) {
    asm volatile(
        "mma.sync.aligned.m16n8k16.row.col.f32.f16.f16.f32 "
        "{%0,%1,%2,%3}, {%4,%5,%6,%7}, {%8,%9}, {%0,%1,%2,%3};"
        : "+f"(c[0]), "+f"(c[1]), "+f"(c[2]), "+f"(c[3])
        : "r"(a[0]), "r"(a[1]), "r"(a[2]), "r"(a[3]), "r"(b[0]), "r"(b[1]));
}

__device__ __forceinline__ void ldsm_x4(uint32_t* r, uint32_t addr) {
    asm volatile("ldmatrix.sync.aligned.m8n8.x4.shared.b16 {%0,%1,%2,%3}, [%4];"
                 : "=r"(r[0]), "=r"(r[1]), "=r"(r[2]), "=r"(r[3]) : "r"(addr));
}
__device__ __forceinline__ void ldsm_x4t(uint32_t* r, uint32_t addr) {
    asm volatile("ldmatrix.sync.aligned.m8n8.x4.trans.shared.b16 {%0,%1,%2,%3}, [%4];"
                 : "=r"(r[0]), "=r"(r[1]), "=r"(r[2]), "=r"(r[3]) : "r"(addr));
}

__device__ __forceinline__ void cp16(uint32_t dst_smem, const void* src, bool pred) {
    int sz = pred ? 16 : 0;   // sz=0 -> 16B zero-fill
    asm volatile("cp.async.ca.shared.global [%0], [%1], 16, %2;"
                 :: "r"(dst_smem), "l"(src), "r"(sz));
}
__device__ __forceinline__ void cp_commit() { asm volatile("cp.async.commit_group;"); }

// ---------------------------------------------------------------------------
// Weight conversion: fp32 [k][n] -> fp16 k-paired [n][k/2] words. One-shot.
// ---------------------------------------------------------------------------
__global__ void cvt_weights(const float* __restrict__ Wq, const float* __restrict__ Wk,
                            const float* __restrict__ Wv, const float* __restrict__ Wo)
{
    __shared__ float tile[32][33];
    const float* W = (blockIdx.z == 0) ? Wq : (blockIdx.z == 1) ? Wk
                   : (blockIdx.z == 2) ? Wv : Wo;
    uint32_t* out = (blockIdx.z == 0) ? g_Wqt : (blockIdx.z == 1) ? g_Wkt
                  : (blockIdx.z == 2) ? g_Wvt : g_Wot;
    int k0 = blockIdx.x * 32, n0 = blockIdx.y * 32;
    int tx = threadIdx.x, ty = threadIdx.y;
    tile[ty][tx] = W[(size_t)(k0 + ty)*CC + n0 + tx];
    __syncthreads();
    if (tx < 16)
        out[(size_t)(n0 + ty)*CW + (k0 >> 1) + tx] =
            packh2(tile[2*tx][ty], tile[2*tx + 1][ty]);
}

// ---------------------------------------------------------------------------
// Fused depthwise 3x3 conv + BN. One block per (b, y): 384 channel-threads,
// 3-row sliding window. Computes q (stride1 SAME) for row y; on odd rows also
// k and v (stride2 VALID) for row yk = (y-1)/2 — same 3 staged input rows.
// x is read 3x total (vs 9x + 2x before).
// ---------------------------------------------------------------------------
__global__ __launch_bounds__(CC)
void dwbn_fused(const float* __restrict__ x,
                const float* __restrict__ wq, const float* __restrict__ qg,
                const float* __restrict__ qb, const float* __restrict__ qm,
                const float* __restrict__ qv,
                const float* __restrict__ wk, const float* __restrict__ kg,
                const float* __restrict__ kb, const float* __restrict__ km,
                const float* __restrict__ kvv,
                const float* __restrict__ wv, const float* __restrict__ vg,
                const float* __restrict__ vb, const float* __restrict__ vm,
                const float* __restrict__ vvv,
                __half* __restrict__ outq, __half* __restrict__ outk,
                __half* __restrict__ outv)
{
    int c = threadIdx.x;
    int by = blockIdx.x;
    int b  = by / HH;
    int y  = by - b * HH;
    bool kvrow = (y & 1) && (y <= 2*(HK-1) + 1);   // y = 2*yk+1, yk 0..12
    int yk = y >> 1;

    // per-channel weights / BN constants
    float Wq9[9], Wk9[9], Wv9[9];
#pragma unroll
    for (int i = 0; i < 9; ++i) Wq9[i] = wq[i*CC + c];
    float scq = qg[c] * rsqrtf(qv[c] + EPSV);
    float shq = qb[c] - scq * qm[c];
    float sck = 0.f, shk = 0.f, scv = 0.f, shv = 0.f;
    if (kvrow) {
#pragma unroll
        for (int i = 0; i < 9; ++i) { Wk9[i] = wk[i*CC + c]; Wv9[i] = wv[i*CC + c]; }
        sck = kg[c] * rsqrtf(kvv[c] + EPSV);
        shk = kb[c] - sck * km[c];
        scv = vg[c] * rsqrtf(vvv[c] + EPSV);
        shv = vb[c] - scv * vm[c];
    }

    const float* xr0 = x + ((size_t)b*TT + (y-1)*WW)*CC + c;   // row y-1
    const float* xr1 = x + ((size_t)b*TT + (y  )*WW)*CC + c;   // row y
    const float* xr2 = x + ((size_t)b*TT + (y+1)*WW)*CC + c;   // row y+1
    bool ok0 = (y > 0), ok2 = (y < HH-1);

    __half* oq = outq + ((size_t)b*TT + y*WW)*CC + c;
    __half* ok_ = outk + ((size_t)b*TK + yk*HK)*CC + c;
    __half* ov_ = outv + ((size_t)b*TK + yk*HK)*CC + c;

    // window: w[dx][dy], dx: 0=col-1(left) 1=center 2=right
    float win[3][3];
#pragma unroll
    for (int dx = 0; dx < 3; ++dx)
#pragma unroll
        for (int dy = 0; dy < 3; ++dy) win[dx][dy] = 0.f;

    for (int col = 0; col <= WW; ++col) {
        // load column 'col' into win[2]
        if (col < WW) {
            size_t off = (size_t)col * CC;
            win[2][0] = ok0 ? xr0[off] : 0.f;
            win[2][1] = xr1[off];
            win[2][2] = ok2 ? xr2[off] : 0.f;
        } else {
            win[2][0] = win[2][1] = win[2][2] = 0.f;
        }

        if (col >= 1) {
            int j = col - 1;   // output column (window cols: 0=j-1, 1=j, 2=j+1)
            float acc = 0.f;
#pragma unroll
            for (int dy = 0; dy < 3; ++dy)
#pragma unroll
                for (int dx = 0; dx < 3; ++dx)
                    acc += win[dx][dy] * Wq9[dy*3 + dx];
            oq[(size_t)j*CC] = __float2half_rn(scq * acc + shq);

            // kv output when col = 2*xk+2 (window cols 0,1,2 = 2xk,2xk+1,2xk+2)
            if (kvrow && col >= 2 && !(col & 1) && col <= 2*(HK-1) + 2) {
                int xk = (col - 2) >> 1;
                float ak = 0.f, av = 0.f;
#pragma unroll
                for (int dy = 0; dy < 3; ++dy)
#pragma unroll
                    for (int dx = 0; dx < 3; ++dx) {
                        float xv = win[dx][dy];
                        ak += xv * Wk9[dy*3 + dx];
                        av += xv * Wv9[dy*3 + dx];
                    }
                ok_[(size_t)xk*CC] = __float2half_rn(sck * ak + shk);
                ov_[(size_t)xk*CC] = __float2half_rn(scv * av + shv);
            }
        }
        // shift window left
#pragma unroll
        for (int dy = 0; dy < 3; ++dy) {
            win[0][dy] = win[1][dy];
            win[1][dy] = win[2][dy];
        }
    }
}

// ---------------------------------------------------------------------------
// FP16 GEMM (ldmatrix, x4 B-loads): C[M,384] = A @ W (+bias).
// 256 threads (8 warps 2m x 4n), block 128x128, warp 64x32, BK=32 halves,
// cp.async double-buffered.
// ---------------------------------------------------------------------------
#define GBM 128
#define GBN 128
#define AST 20
#define BST 20
#define NT  12           // 384/32

__global__ __launch_bounds__(256, 2)
void gemm_f16(const __half* __restrict__ A, const uint32_t* __restrict__ W2,
              const float* __restrict__ bias, __half* __restrict__ Ch,
              float* __restrict__ Cf, int M)
{
    __shared__ uint32_t As[2][GBM*AST];
    __shared__ uint32_t Bs[2][GBN*BST];

    int tid  = threadIdx.x;
    int warp = tid >> 5;
    int lane = tid & 31;
    int g    = lane >> 2;
    int tg   = lane & 3;
    int bm   = blockIdx.x * GBM;
    int bn   = blockIdx.y * GBN;
    int wm   = (warp >> 2) * 64;
    int wn   = (warp & 3) * 32;

    int l_r = tid >> 2;
    int l_q = (tid & 3) * 4;

    // ldmatrix lane offsets
    int a_row = (lane & 7) | (lane & 8);   // 0..15
    int a_kof = (lane >> 4) << 2;          // 0 or 4
    // B x4: lanes 0-15 -> n-block nf, lanes 16-31 -> nf+1
    int b_rowp = ((lane >> 4) & 1) * 8 + (lane & 7);  // row within 16-row pair
    int b_kof  = (lane & 8) ? 4 : 0;

    uint32_t sA[2], sB[2];
    sA[0] = (uint32_t)__cvta_generic_to_shared(&As[0][0]);
    sA[1] = (uint32_t)__cvta_generic_to_shared(&As[1][0]);
    sB[0] = (uint32_t)__cvta_generic_to_shared(&Bs[0][0]);
    sB[1] = (uint32_t)__cvta_generic_to_shared(&Bs[1][0]);

    float acc[4][4][4];
#pragma unroll
    for (int mf = 0; mf < 4; ++mf)
#pragma unroll
        for (int nf = 0; nf < 4; ++nf)
#pragma unroll
            for (int c = 0; c < 4; ++c) acc[mf][nf][c] = 0.f;

    auto load_stage = [&](int t, int buf) {
#pragma unroll
        for (int i = 0; i < 2; ++i) {
            int r  = i*64 + l_r;
            int gr = bm + r;
            bool p = (gr < M);
            const __half* src = &A[(size_t)(p ? gr : 0)*CC + t*32 + l_q*2];
            cp16(sA[buf] + (uint32_t)(r*AST + l_q)*4u, src, p);
        }
#pragma unroll
        for (int i = 0; i < 2; ++i) {
            int n = i*64 + l_r;
            const uint32_t* src = &W2[(size_t)(bn + n)*CW + t*16 + l_q];
            cp16(sB[buf] + (uint32_t)(n*BST + l_q)*4u, src, true);
        }
        cp_commit();
    };

    load_stage(0, 0);

    for (int t = 0; t < NT; ++t) {
        int buf = t & 1;
        if (t + 1 < NT) {
            load_stage(t + 1, buf ^ 1);
            asm volatile("cp.async.wait_group 1;");
        } else {
            asm volatile("cp.async.wait_group 0;");
        }
        __syncthreads();

        uint32_t ab = sA[buf];
        uint32_t bb = sB[buf];
#pragma unroll
        for (int s = 0; s < 2; ++s) {
            int kw = s * 8;
            uint32_t af[4][4], bf[4][2];
#pragma unroll
            for (int mf = 0; mf < 4; ++mf)
                ldsm_x4(af[mf], ab + 4u*((wm + mf*16 + a_row)*AST + kw + a_kof));
#pragma unroll
            for (int nf2 = 0; nf2 < 2; ++nf2) {
                uint32_t q[4];
                ldsm_x4(q, bb + 4u*((wn + nf2*16 + b_rowp)*BST + kw + b_kof));
                bf[nf2*2  ][0] = q[0]; bf[nf2*2  ][1] = q[1];
                bf[nf2*2+1][0] = q[2]; bf[nf2*2+1][1] = q[3];
            }
#pragma unroll
            for (int nf = 0; nf < 4; ++nf)
#pragma unroll
                for (int mf = 0; mf < 4; ++mf)
                    mma16(acc[mf][nf], af[mf], bf[nf]);
        }
        __syncthreads();
    }

    // Epilogue
#pragma unroll
    for (int mf = 0; mf < 4; ++mf) {
#pragma unroll
        for (int i = 0; i < 2; ++i) {
            int gr = bm + wm + mf*16 + g + i*8;
            if (gr >= M) continue;
#pragma unroll
            for (int nf = 0; nf < 4; ++nf) {
                int col = bn + wn + nf*8 + tg*2;
                if (Cf) {
                    float2 v;
                    v.x = acc[mf][nf][i*2 + 0] + bias[col];
                    v.y = acc[mf][nf][i*2 + 1] + bias[col+1];
                    *(float2*)&Cf[(size_t)gr*CC + col] = v;
                } else {
                    uint32_t w = packh2(acc[mf][nf][i*2 + 0], acc[mf][nf][i*2 + 1]);
                    *(uint32_t*)&Ch[(size_t)gr*CC + col] = w;
                }
            }
        }
    }
}

// ---------------------------------------------------------------------------
// FP16 attention: cp.async staging, ldmatrix (x4) fragments, register-resident
// S/P. 8 warps x 16 q-rows = 128 rows/block.
// ---------------------------------------------------------------------------
#define JP   176
#define NKC  22
#define QST  36
#define KST  36
#define VST  36

__global__ __launch_bounds__(256, 2)
void attn_f16(const __half* __restrict__ Q, const __half* __restrict__ K,
              const __half* __restrict__ V, __half* __restrict__ O)
{
    extern __shared__ uint32_t sm[];
    uint32_t* Qs = sm;
    uint32_t* Ks = Qs + 128*QST;
    uint32_t* Vs = Ks + JP*KST;

    int tid  = threadIdx.x;
    int warp = tid >> 5;
    int lane = tid & 31;
    int g    = lane >> 2;
    int tg   = lane & 3;
    int bh   = blockIdx.y;
    int b    = bh / NHEAD;
    int h    = bh - b * NHEAD;
    int row0 = blockIdx.x * 128;
    const float scale = rsqrtf((float)CC);

    int a_row  = (lane & 7) | (lane & 8);
    int a_kof  = (lane >> 4) << 2;
    int b_rowp = ((lane >> 4) & 1) * 8 + (lane & 7);
    int b_kof  = (lane & 8) ? 4 : 0;

    uint32_t qb = (uint32_t)__cvta_generic_to_shared(Qs);
    uint32_t kb = (uint32_t)__cvta_generic_to_shared(Ks);
    uint32_t vb = (uint32_t)__cvta_generic_to_shared(Vs);

    const uint32_t* Qw = (const uint32_t*)Q + (size_t)b*TT*CW + h*32;
    const uint32_t* Kw = (const uint32_t*)K + (size_t)b*TK*CW + h*32;
    const uint32_t* Vw = (const uint32_t*)V + (size_t)b*TK*CW + h*32;

    for (int idx = tid; idx < 128*8; idx += 256) {
        int r = idx >> 3, c4 = (idx & 7) * 4;
        int gr = row0 + r;
        bool p = (gr < TT);
        cp16(qb + 4u*(r*QST + c4), Qw + (size_t)(p ? gr : 0)*CW + c4, p);
    }
    for (int idx = tid; idx < JP*8; idx += 256) {
        int j = idx >> 3, c4 = (idx & 7) * 4;
        bool p = (j < TK);
        int js = p ? j : 0;
        cp16(kb + 4u*(j*KST + c4), Kw + (size_t)js*CW + c4, p);
        cp16(vb + 4u*(j*VST + c4), Vw + (size_t)js*CW + c4, p);
    }
    cp_commit();
    asm volatile("cp.async.wait_group 0;");
    __syncthreads();

    int r0 = row0 + warp * 16;

    float p[NKC][4];
#pragma unroll
    for (int ni = 0; ni < NKC; ++ni)
#pragma unroll
        for (int c = 0; c < 4; ++c) p[ni][c] = 0.f;

#pragma unroll
    for (int kc = 0; kc < 4; ++kc) {
        int kw = kc * 8;
        uint32_t af[4];
        ldsm_x4(af, qb + 4u*((warp*16 + a_row)*QST + kw + a_kof));
#pragma unroll
        for (int np = 0; np < NKC/2; ++np) {
            uint32_t q[4];
            ldsm_x4(q, kb + 4u*((np*16 + b_rowp)*KST + kw + b_kof));
            uint32_t bf0[2] = { q[0], q[1] };
            uint32_t bf1[2] = { q[2], q[3] };
            mma16(p[np*2    ], af, bf0);
            mma16(p[np*2 + 1], af, bf1);
        }
    }

    float m0 = -1e30f, m1 = -1e30f;
#pragma unroll
    for (int ni = 0; ni < NKC; ++ni) {
        int c0 = ni*8 + 2*tg, c1 = c0 + 1;
        p[ni][0] = (c0 < TK) ? p[ni][0]*scale : -1e30f;
        p[ni][1] = (c1 < TK) ? p[ni][1]*scale : -1e30f;
        p[ni][2] = (c0 < TK) ? p[ni][2]*scale : -1e30f;
        p[ni][3] = (c1 < TK) ? p[ni][3]*scale : -1e30f;
        m0 = fmaxf(m0, fmaxf(p[ni][0], p[ni][1]));
        m1 = fmaxf(m1, fmaxf(p[ni][2], p[ni][3]));
    }
    m0 = fmaxf(m0, __shfl_xor_sync(~0u, m0, 1));
    m0 = fmaxf(m0, __shfl_xor_sync(~0u, m0, 2));
    m1 = fmaxf(m1, __shfl_xor_sync(~0u, m1, 1));
    m1 = fmaxf(m1, __shfl_xor_sync(~0u, m1, 2));

    float s0 = 0.f, s1 = 0.f;
#pragma unroll
    for (int ni = 0; ni < NKC; ++ni) {
        p[ni][0] = __expf(p[ni][0] - m0);
        p[ni][1] = __expf(p[ni][1] - m0);
        p[ni][2] = __expf(p[ni][2] - m1);
        p[ni][3] = __expf(p[ni][3] - m1);
        s0 += p[ni][0] + p[ni][1];
        s1 += p[ni][2] + p[ni][3];
    }
    s0 += __shfl_xor_sync(~0u, s0, 1);
    s0 += __shfl_xor_sync(~0u, s0, 2);
    s1 += __shfl_xor_sync(~0u, s1, 1);
    s1 += __shfl_xor_sync(~0u, s1, 2);
    float i0 = 1.f / s0, i1 = 1.f / s1;

    uint32_t p2[2*NKC];
#pragma unroll
    for (int ni = 0; ni < NKC; ++ni) {
        p2[2*ni    ] = packh2(p[ni][0]*i0, p[ni][1]*i0);
        p2[2*ni + 1] = packh2(p[ni][2]*i1, p[ni][3]*i1);
    }

    float oacc[8][4];
#pragma unroll
    for (int nf = 0; nf < 8; ++nf)
#pragma unroll
        for (int c = 0; c < 4; ++c) oacc[nf][c] = 0.f;

#pragma unroll
    for (int kc = 0; kc < 11; ++kc) {
        uint32_t af[4];
        af[0] = p2[4*kc    ];
        af[1] = p2[4*kc + 1];
        af[2] = p2[4*kc + 2];
        af[3] = p2[4*kc + 3];
        int jr = kc * 16;
#pragma unroll
        for (int np = 0; np < 4; ++np) {
            uint32_t q[4];
            // x4.trans: lanes 0-15 -> d-block 2np, lanes 16-31 -> 2np+1
            ldsm_x4t(q, vb + 4u*((jr + a_row)*VST + (np*2 + (lane >> 4))*4));
            uint32_t bf0[2] = { q[0], q[1] };
            uint32_t bf1[2] = { q[2], q[3] };
            mma16(oacc[np*2    ], af, bf0);
            mma16(oacc[np*2 + 1], af, bf1);
        }
    }

#pragma unroll
    for (int nf = 0; nf < 8; ++nf) {
#pragma unroll
        for (int i = 0; i < 2; ++i) {
            int gr = r0 + g + i*8;
            if (gr >= TT) continue;
            int col = h*DD + nf*8 + tg*2;
            uint32_t w = packh2(oacc[nf][i*2 + 0], oacc[nf][i*2 + 1]);
            *(uint32_t*)&O[((size_t)b*TT + gr)*CC + col] = w;
        }
    }
}

static const int ATTN_SMEM = (128*QST + JP*KST + JP*VST) * (int)sizeof(uint32_t); // 69120

extern "C" void kernel_launch(void* const* d_in, const int* in_sizes, int n_in,
                              void* d_out, int out_size)
{
    (void)in_sizes; (void)n_in; (void)out_size;
    const float* x   = (const float*)d_in[0];
    const float* wq  = (const float*)d_in[1];
    const float* qg  = (const float*)d_in[2];
    const float* qb  = (const float*)d_in[3];
    const float* qm  = (const float*)d_in[4];
    const float* qv  = (const float*)d_in[5];
    const float* wk  = (const float*)d_in[6];
    const float* kg  = (const float*)d_in[7];
    const float* kb  = (const float*)d_in[8];
    const float* km  = (const float*)d_in[9];
    const float* kv_ = (const float*)d_in[10];
    const float* wv  = (const float*)d_in[11];
    const float* vg  = (const float*)d_in[12];
    const float* vb  = (const float*)d_in[13];
    const float* vm  = (const float*)d_in[14];
    const float* vv_ = (const float*)d_in[15];
    const float* Wq  = (const float*)d_in[16];
    const float* Wk  = (const float*)d_in[17];
    const float* Wv  = (const float*)d_in[18];
    const float* Wo  = (const float*)d_in[19];
    const float* bo  = (const float*)d_in[20];
    float* out = (float*)d_out;

    __half *qc, *kc, *vc, *Qp, *Kp, *Vp, *Op;
    uint32_t *Wqt, *Wkt, *Wvt, *Wot;
    cudaGetSymbolAddress((void**)&qc, g_qc);
    cudaGetSymbolAddress((void**)&kc, g_kc);
    cudaGetSymbolAddress((void**)&vc, g_vc);
    cudaGetSymbolAddress((void**)&Qp, g_Q);
    cudaGetSymbolAddress((void**)&Kp, g_K);
    cudaGetSymbolAddress((void**)&Vp, g_V);
    cudaGetSymbolAddress((void**)&Op, g_O);
    cudaGetSymbolAddress((void**)&Wqt, g_Wqt);
    cudaGetSymbolAddress((void**)&Wkt, g_Wkt);
    cudaGetSymbolAddress((void**)&Wvt, g_Wvt);
    cudaGetSymbolAddress((void**)&Wot, g_Wot);

    // 0. weight conversion
    dim3 wg(CC/32, CC/32, 4);
    cvt_weights<<<wg, dim3(32,32)>>>(Wq, Wk, Wv, Wo);

    // 1. fused conv projections (q + k + v, x read once per 3-row band)
    dwbn_fused<<<BB*HH, CC>>>(x, wq, qg, qb, qm, qv,
                              wk, kg, kb, km, kv_,
                              wv, vg, vb, vm, vv_, qc, kc, vc);

    // 2. dense projections
    const int MQ = BB*TT;   // 50176
    const int MK = BB*TK;   // 10816
    dim3 gq((MQ + GBM - 1)/GBM, CC/GBN);   // 392 x 3
    dim3 gk((MK + GBM - 1)/GBM, CC/GBN);   // 85 x 3
    gemm_f16<<<gq, 256>>>(qc, Wqt, nullptr, Qp, nullptr, MQ);
    gemm_f16<<<gk, 256>>>(kc, Wkt, nullptr, Kp, nullptr, MK);
    gemm_f16<<<gk, 256>>>(vc, Wvt, nullptr, Vp, nullptr, MK);

    // 3. attention
    cudaFuncSetAttribute(attn_f16, cudaFuncAttributeMaxDynamicSharedMemorySize, ATTN_SMEM);
    dim3 ga((TT + 127)/128, BB*NHEAD);   // 7 x 384
    attn_f16<<<ga, 256, ATTN_SMEM>>>(Qp, Kp, Vp, Op);

    // 4. output projection (+bias, fp32 out)
    gemm_f16<<<gq, 256>>>(Op, Wot, bo, nullptr, out, MQ);
}

// round 10
// speedup vs baseline: 2.3666x; 1.1422x over previous
#include <cuda_runtime.h>
#include <cuda_fp16.h>
#include <math.h>
#include <stdint.h>

// Problem constants
#define BB   64
#define HH   28
#define WW   28
#define CC   384
#define TT   784      // HH*WW
#define HK   13       // (28-3)/2+1
#define TK   169      // 13*13
#define NHEAD 6
#define DD   64
#define EPSV 1e-3f
#define CW   (CC/2)   // 192 half2-words per row

// Scratch (device globals). Activations fp16; weights k-paired [n][k/2].
__device__ __half  g_qc[(size_t)BB*TT*CC];
__device__ __half  g_kc[(size_t)BB*TK*CC];
__device__ __half  g_vc[(size_t)BB*TK*CC];
__device__ __half  g_Q [(size_t)BB*TT*CC];
__device__ __half  g_K [(size_t)BB*TK*CC];
__device__ __half  g_V [(size_t)BB*TK*CC];
__device__ __half  g_O [(size_t)BB*TT*CC];
__device__ uint32_t g_Wqt[(size_t)CC*CW];
__device__ uint32_t g_Wkt[(size_t)CC*CW];
__device__ uint32_t g_Wvt[(size_t)CC*CW];
__device__ uint32_t g_Wot[(size_t)CC*CW];

// ---------------------------------------------------------------------------
// helpers
// ---------------------------------------------------------------------------
__device__ __forceinline__ uint32_t packh2(float a, float b) {
    __half2 h = __floats2half2_rn(a, b);
    return *reinterpret_cast<uint32_t*>(&h);
}

__device__ __forceinline__ void mma16(float* c, const uint32_t* a, const uint32_t* b) {
    asm volatile(
        "mma.sync.aligned.m16n8k16.row.col.f32.f16.f16.f32 "
        "{%0,%1,%2,%3}, {%4,%5,%6,%7}, {%8,%9}, {%0,%1,%2,%3};"
        : "+f"(c[0]), "+f"(c[1]), "+f"(c[2]), "+f"(c[3])
        : "r"(a[0]), "r"(a[1]), "r"(a[2]), "r"(a[3]), "r"(b[0]), "r"(b[1]));
}

__device__ __forceinline__ void ldsm_x4(uint32_t* r, uint32_t addr) {
    asm volatile("ldmatrix.sync.aligned.m8n8.x4.shared.b16 {%0,%1,%2,%3}, [%4];"
                 : "=r"(r[0]), "=r"(r[1]), "=r"(r[2]), "=r"(r[3]) : "r"(addr));
}
__device__ __forceinline__ void ldsm_x4t(uint32_t* r, uint32_t addr) {
    asm volatile("ldmatrix.sync.aligned.m8n8.x4.trans.shared.b16 {%0,%1,%2,%3}, [%4];"
                 : "=r"(r[0]), "=r"(r[1]), "=r"(r[2]), "=r"(r[3]) : "r"(addr));
}

__device__ __forceinline__ void cp16(uint32_t dst_smem, const void* src, bool pred) {
    int sz = pred ? 16 : 0;   // sz=0 -> 16B zero-fill
    asm volatile("cp.async.ca.shared.global [%0], [%1], 16, %2;"
                 :: "r"(dst_smem), "l"(src), "r"(sz));
}
__device__ __forceinline__ void cp_commit() { asm volatile("cp.async.commit_group;"); }

// ---------------------------------------------------------------------------
// Weight conversion: fp32 [k][n] -> fp16 k-paired [n][k/2] words. One-shot.
// ---------------------------------------------------------------------------
__global__ void cvt_weights(const float* __restrict__ Wq, const float* __restrict__ Wk,
                            const float* __restrict__ Wv, const float* __restrict__ Wo)
{
    __shared__ float tile[32][33];
    const float* W = (blockIdx.z == 0) ? Wq : (blockIdx.z == 1) ? Wk
                   : (blockIdx.z == 2) ? Wv : Wo;
    uint32_t* out = (blockIdx.z == 0) ? g_Wqt : (blockIdx.z == 1) ? g_Wkt
                  : (blockIdx.z == 2) ? g_Wvt : g_Wot;
    int k0 = blockIdx.x * 32, n0 = blockIdx.y * 32;
    int tx = threadIdx.x, ty = threadIdx.y;
    tile[ty][tx] = W[(size_t)(k0 + ty)*CC + n0 + tx];
    __syncthreads();
    if (tx < 16)
        out[(size_t)(n0 + ty)*CW + (k0 >> 1) + tx] =
            packh2(tile[2*tx][ty], tile[2*tx + 1][ty]);
}

// ---------------------------------------------------------------------------
// Fused depthwise 3x3 conv + BN (q stride1 SAME; k,v stride2 VALID on odd rows)
// One block per (b, y), 384 channel-threads, 3-row sliding window.
// ---------------------------------------------------------------------------
__global__ __launch_bounds__(CC)
void dwbn_fused(const float* __restrict__ x,
                const float* __restrict__ wq, const float* __restrict__ qg,
                const float* __restrict__ qb, const float* __restrict__ qm,
                const float* __restrict__ qv,
                const float* __restrict__ wk, const float* __restrict__ kg,
                const float* __restrict__ kb, const float* __restrict__ km,
                const float* __restrict__ kvv,
                const float* __restrict__ wv, const float* __restrict__ vg,
                const float* __restrict__ vb, const float* __restrict__ vm,
                const float* __restrict__ vvv,
                __half* __restrict__ outq, __half* __restrict__ outk,
                __half* __restrict__ outv)
{
    int c = threadIdx.x;
    int by = blockIdx.x;
    int b  = by / HH;
    int y  = by - b * HH;
    bool kvrow = (y & 1) && (y <= 2*(HK-1) + 1);
    int yk = y >> 1;

    float Wq9[9], Wk9[9], Wv9[9];
#pragma unroll
    for (int i = 0; i < 9; ++i) Wq9[i] = wq[i*CC + c];
    float scq = qg[c] * rsqrtf(qv[c] + EPSV);
    float shq = qb[c] - scq * qm[c];
    float sck = 0.f, shk = 0.f, scv = 0.f, shv = 0.f;
    if (kvrow) {
#pragma unroll
        for (int i = 0; i < 9; ++i) { Wk9[i] = wk[i*CC + c]; Wv9[i] = wv[i*CC + c]; }
        sck = kg[c] * rsqrtf(kvv[c] + EPSV);
        shk = kb[c] - sck * km[c];
        scv = vg[c] * rsqrtf(vvv[c] + EPSV);
        shv = vb[c] - scv * vm[c];
    }

    const float* xr0 = x + ((size_t)b*TT + (y-1)*WW)*CC + c;
    const float* xr1 = x + ((size_t)b*TT + (y  )*WW)*CC + c;
    const float* xr2 = x + ((size_t)b*TT + (y+1)*WW)*CC + c;
    bool ok0 = (y > 0), ok2 = (y < HH-1);

    __half* oq  = outq + ((size_t)b*TT + y*WW)*CC + c;
    __half* ok_ = outk + ((size_t)b*TK + yk*HK)*CC + c;
    __half* ov_ = outv + ((size_t)b*TK + yk*HK)*CC + c;

    float win[3][3];
#pragma unroll
    for (int dx = 0; dx < 3; ++dx)
#pragma unroll
        for (int dy = 0; dy < 3; ++dy) win[dx][dy] = 0.f;

    for (int col = 0; col <= WW; ++col) {
        if (col < WW) {
            size_t off = (size_t)col * CC;
            win[2][0] = ok0 ? xr0[off] : 0.f;
            win[2][1] = xr1[off];
            win[2][2] = ok2 ? xr2[off] : 0.f;
        } else {
            win[2][0] = win[2][1] = win[2][2] = 0.f;
        }

        if (col >= 1) {
            int j = col - 1;
            float acc = 0.f;
#pragma unroll
            for (int dy = 0; dy < 3; ++dy)
#pragma unroll
                for (int dx = 0; dx < 3; ++dx)
                    acc += win[dx][dy] * Wq9[dy*3 + dx];
            oq[(size_t)j*CC] = __float2half_rn(scq * acc + shq);

            if (kvrow && col >= 2 && !(col & 1) && col <= 2*(HK-1) + 2) {
                int xk = (col - 2) >> 1;
                float ak = 0.f, av = 0.f;
#pragma unroll
                for (int dy = 0; dy < 3; ++dy)
#pragma unroll
                    for (int dx = 0; dx < 3; ++dx) {
                        float xv = win[dx][dy];
                        ak += xv * Wk9[dy*3 + dx];
                        av += xv * Wv9[dy*3 + dx];
                    }
                ok_[(size_t)xk*CC] = __float2half_rn(sck * ak + shk);
                ov_[(size_t)xk*CC] = __float2half_rn(scv * av + shv);
            }
        }
#pragma unroll
        for (int dy = 0; dy < 3; ++dy) {
            win[0][dy] = win[1][dy];
            win[1][dy] = win[2][dy];
        }
    }
}

// ---------------------------------------------------------------------------
// FP16 GEMM body: 3-stage cp.async pipeline, ONE syncthreads per K-iter.
// 256 threads (8 warps 2m x 4n), block 128x128, warp 64x32, BK=32 halves.
// Dynamic smem: 3 stages x (A 10240B + B 10240B) = 61440B.
// ---------------------------------------------------------------------------
#define AST 20
#define BST 20
#define NT  12           // 384/32
#define STG 3
#define STAGE_B 20480u

__device__ __forceinline__ void gemm_body(
    const __half* __restrict__ A, const uint32_t* __restrict__ W2,
    const float* __restrict__ bias, __half* __restrict__ Ch,
    float* __restrict__ Cf, int M, int bm, int bn, uint32_t smem_u, int tid)
{
    int warp = tid >> 5;
    int lane = tid & 31;
    int g    = lane >> 2;
    int tg   = lane & 3;
    int wm   = (warp >> 2) * 64;
    int wn   = (warp & 3) * 32;

    int l_r = tid >> 2;
    int l_q = (tid & 3) * 4;

    int a_row  = (lane & 7) | (lane & 8);
    int a_kof  = (lane >> 4) << 2;
    int b_rowp = ((lane >> 4) & 1) * 8 + (lane & 7);
    int b_kof  = (lane & 8) ? 4 : 0;

    float acc[4][4][4];
#pragma unroll
    for (int mf = 0; mf < 4; ++mf)
#pragma unroll
        for (int nf = 0; nf < 4; ++nf)
#pragma unroll
            for (int c = 0; c < 4; ++c) acc[mf][nf][c] = 0.f;

    auto load_stage = [&](int t) {
        uint32_t base = smem_u + (uint32_t)(t % STG) * STAGE_B;
#pragma unroll
        for (int i = 0; i < 2; ++i) {
            int r  = i*64 + l_r;
            int gr = bm + r;
            bool p = (gr < M);
            cp16(base + (uint32_t)(r*AST + l_q)*4u,
                 A + (size_t)(p ? gr : 0)*CC + t*32 + l_q*2, p);
        }
#pragma unroll
        for (int i = 0; i < 2; ++i) {
            int n = i*64 + l_r;
            cp16(base + 10240u + (uint32_t)(n*BST + l_q)*4u,
                 W2 + (size_t)(bn + n)*CW + t*16 + l_q, true);
        }
        cp_commit();
    };

    load_stage(0);
    load_stage(1);

    for (int t = 0; t < NT; ++t) {
        if (t + 1 < NT) asm volatile("cp.async.wait_group 1;");
        else            asm volatile("cp.async.wait_group 0;");
        __syncthreads();
        if (t + 2 < NT) load_stage(t + 2);   // buffer (t-1)%3: all warps done with it

        uint32_t base = smem_u + (uint32_t)(t % STG) * STAGE_B;
        uint32_t ab = base;
        uint32_t bb = base + 10240u;
#pragma unroll
        for (int s = 0; s < 2; ++s) {
            int kw = s * 8;
            uint32_t af[4][4], bf[4][2];
#pragma unroll
            for (int mf = 0; mf < 4; ++mf)
                ldsm_x4(af[mf], ab + 4u*((wm + mf*16 + a_row)*AST + kw + a_kof));
#pragma unroll
            for (int nf2 = 0; nf2 < 2; ++nf2) {
                uint32_t q[4];
                ldsm_x4(q, bb + 4u*((wn + nf2*16 + b_rowp)*BST + kw + b_kof));
                bf[nf2*2  ][0] = q[0]; bf[nf2*2  ][1] = q[1];
                bf[nf2*2+1][0] = q[2]; bf[nf2*2+1][1] = q[3];
            }
#pragma unroll
            for (int nf = 0; nf < 4; ++nf)
#pragma unroll
                for (int mf = 0; mf < 4; ++mf)
                    mma16(acc[mf][nf], af[mf], bf[nf]);
        }
    }

#pragma unroll
    for (int mf = 0; mf < 4; ++mf) {
#pragma unroll
        for (int i = 0; i < 2; ++i) {
            int gr = bm + wm + mf*16 + g + i*8;
            if (gr >= M) continue;
#pragma unroll
            for (int nf = 0; nf < 4; ++nf) {
                int col = bn + wn + nf*8 + tg*2;
                if (Cf) {
                    float2 v;
                    v.x = acc[mf][nf][i*2 + 0] + bias[col];
                    v.y = acc[mf][nf][i*2 + 1] + bias[col+1];
                    *(float2*)&Cf[(size_t)gr*CC + col] = v;
                } else {
                    uint32_t w = packh2(acc[mf][nf][i*2 + 0], acc[mf][nf][i*2 + 1]);
                    *(uint32_t*)&Ch[(size_t)gr*CC + col] = w;
                }
            }
        }
    }
}

// Merged Q/K/V projection: flattened grid (1176 Q + 255 K + 255 V = 1686)
__global__ __launch_bounds__(256, 2)
void gemm_qkv(const __half* __restrict__ qc, const __half* __restrict__ kc,
              const __half* __restrict__ vc,
              const uint32_t* __restrict__ Wq2, const uint32_t* __restrict__ Wk2,
              const uint32_t* __restrict__ Wv2,
              __half* __restrict__ Qp, __half* __restrict__ Kp,
              __half* __restrict__ Vp)
{
    extern __shared__ __align__(16) char smem[];
    uint32_t smem_u = (uint32_t)__cvta_generic_to_shared(smem);
    int idx = blockIdx.x;
    const __half* A; const uint32_t* W2; __half* Ch; int M; int tile;
    if (idx < 1176)      { A = qc; W2 = Wq2; Ch = Qp; M = BB*TT; tile = idx; }
    else if (idx < 1431) { A = kc; W2 = Wk2; Ch = Kp; M = BB*TK; tile = idx - 1176; }
    else                 { A = vc; W2 = Wv2; Ch = Vp; M = BB*TK; tile = idx - 1431; }
    int mtiles = (M + 127) >> 7;
    int bm = (tile % mtiles) * 128;
    int bn = (tile / mtiles) * 128;
    gemm_body(A, W2, nullptr, Ch, nullptr, M, bm, bn, smem_u, threadIdx.x);
}

// Output projection (+bias, fp32 out)
__global__ __launch_bounds__(256, 2)
void gemm_out(const __half* __restrict__ Op, const uint32_t* __restrict__ Wo2,
              const float* __restrict__ bo, float* __restrict__ out)
{
    extern __shared__ __align__(16) char smem[];
    uint32_t smem_u = (uint32_t)__cvta_generic_to_shared(smem);
    int tile = blockIdx.x;
    int bm = (tile % 392) * 128;
    int bn = (tile / 392) * 128;
    gemm_body(Op, Wo2, bo, nullptr, out, BB*TT, bm, bn, smem_u, threadIdx.x);
}

// ---------------------------------------------------------------------------
// FP16 attention (R9, passing): cp.async staging, ldmatrix x4 fragments,
// register-resident S/P. 8 warps x 16 q-rows = 128 rows/block.
// ---------------------------------------------------------------------------
#define JP   176
#define NKC  22
#define QST  36
#define KST  36
#define VST  36

__global__ __launch_bounds__(256, 2)
void attn_f16(const __half* __restrict__ Q, const __half* __restrict__ K,
              const __half* __restrict__ V, __half* __restrict__ O)
{
    extern __shared__ uint32_t sm[];
    uint32_t* Qs = sm;
    uint32_t* Ks = Qs + 128*QST;
    uint32_t* Vs = Ks + JP*KST;

    int tid  = threadIdx.x;
    int warp = tid >> 5;
    int lane = tid & 31;
    int g    = lane >> 2;
    int tg   = lane & 3;
    int bh   = blockIdx.y;
    int b    = bh / NHEAD;
    int h    = bh - b * NHEAD;
    int row0 = blockIdx.x * 128;
    const float scale = rsqrtf((float)CC);

    int a_row  = (lane & 7) | (lane & 8);
    int a_kof  = (lane >> 4) << 2;
    int b_rowp = ((lane >> 4) & 1) * 8 + (lane & 7);
    int b_kof  = (lane & 8) ? 4 : 0;

    uint32_t qb = (uint32_t)__cvta_generic_to_shared(Qs);
    uint32_t kb = (uint32_t)__cvta_generic_to_shared(Ks);
    uint32_t vb = (uint32_t)__cvta_generic_to_shared(Vs);

    const uint32_t* Qw = (const uint32_t*)Q + (size_t)b*TT*CW + h*32;
    const uint32_t* Kw = (const uint32_t*)K + (size_t)b*TK*CW + h*32;
    const uint32_t* Vw = (const uint32_t*)V + (size_t)b*TK*CW + h*32;

    for (int idx = tid; idx < 128*8; idx += 256) {
        int r = idx >> 3, c4 = (idx & 7) * 4;
        int gr = row0 + r;
        bool p = (gr < TT);
        cp16(qb + 4u*(r*QST + c4), Qw + (size_t)(p ? gr : 0)*CW + c4, p);
    }
    for (int idx = tid; idx < JP*8; idx += 256) {
        int j = idx >> 3, c4 = (idx & 7) * 4;
        bool p = (j < TK);
        int js = p ? j : 0;
        cp16(kb + 4u*(j*KST + c4), Kw + (size_t)js*CW + c4, p);
        cp16(vb + 4u*(j*VST + c4), Vw + (size_t)js*CW + c4, p);
    }
    cp_commit();
    asm volatile("cp.async.wait_group 0;");
    __syncthreads();

    int r0 = row0 + warp * 16;

    float p[NKC][4];
#pragma unroll
    for (int ni = 0; ni < NKC; ++ni)
#pragma unroll
        for (int c = 0; c < 4; ++c) p[ni][c] = 0.f;

#pragma unroll
    for (int kc = 0; kc < 4; ++kc) {
        int kw = kc * 8;
        uint32_t af[4];
        ldsm_x4(af, qb + 4u*((warp*16 + a_row)*QST + kw + a_kof));
#pragma unroll
        for (int np = 0; np < NKC/2; ++np) {
            uint32_t q[4];
            ldsm_x4(q, kb + 4u*((np*16 + b_rowp)*KST + kw + b_kof));
            uint32_t bf0[2] = { q[0], q[1] };
            uint32_t bf1[2] = { q[2], q[3] };
            mma16(p[np*2    ], af, bf0);
            mma16(p[np*2 + 1], af, bf1);
        }
    }

    float m0 = -1e30f, m1 = -1e30f;
#pragma unroll
    for (int ni = 0; ni < NKC; ++ni) {
        int c0 = ni*8 + 2*tg, c1 = c0 + 1;
        p[ni][0] = (c0 < TK) ? p[ni][0]*scale : -1e30f;
        p[ni][1] = (c1 < TK) ? p[ni][1]*scale : -1e30f;
        p[ni][2] = (c0 < TK) ? p[ni][2]*scale : -1e30f;
        p[ni][3] = (c1 < TK) ? p[ni][3]*scale : -1e30f;
        m0 = fmaxf(m0, fmaxf(p[ni][0], p[ni][1]));
        m1 = fmaxf(m1, fmaxf(p[ni][2], p[ni][3]));
    }
    m0 = fmaxf(m0, __shfl_xor_sync(~0u, m0, 1));
    m0 = fmaxf(m0, __shfl_xor_sync(~0u, m0, 2));
    m1 = fmaxf(m1, __shfl_xor_sync(~0u, m1, 1));
    m1 = fmaxf(m1, __shfl_xor_sync(~0u, m1, 2));

    float s0 = 0.f, s1 = 0.f;
#pragma unroll
    for (int ni = 0; ni < NKC; ++ni) {
        p[ni][0] = __expf(p[ni][0] - m0);
        p[ni][1] = __expf(p[ni][1] - m0);
        p[ni][2] = __expf(p[ni][2] - m1);
        p[ni][3] = __expf(p[ni][3] - m1);
        s0 += p[ni][0] + p[ni][1];
        s1 += p[ni][2] + p[ni][3];
    }
    s0 += __shfl_xor_sync(~0u, s0, 1);
    s0 += __shfl_xor_sync(~0u, s0, 2);
    s1 += __shfl_xor_sync(~0u, s1, 1);
    s1 += __shfl_xor_sync(~0u, s1, 2);
    float i0 = 1.f / s0, i1 = 1.f / s1;

    uint32_t p2[2*NKC];
#pragma unroll
    for (int ni = 0; ni < NKC; ++ni) {
        p2[2*ni    ] = packh2(p[ni][0]*i0, p[ni][1]*i0);
        p2[2*ni + 1] = packh2(p[ni][2]*i1, p[ni][3]*i1);
    }

    float oacc[8][4];
#pragma unroll
    for (int nf = 0; nf < 8; ++nf)
#pragma unroll
        for (int c = 0; c < 4; ++c) oacc[nf][c] = 0.f;

#pragma unroll
    for (int kc = 0; kc < 11; ++kc) {
        uint32_t af[4];
        af[0] = p2[4*kc    ];
        af[1] = p2[4*kc + 1];
        af[2] = p2[4*kc + 2];
        af[3] = p2[4*kc + 3];
        int jr = kc * 16;
#pragma unroll
        for (int np = 0; np < 4; ++np) {
            uint32_t q[4];
            ldsm_x4t(q, vb + 4u*((jr + a_row)*VST + (np*2 + (lane >> 4))*4));
            uint32_t bf0[2] = { q[0], q[1] };
            uint32_t bf1[2] = { q[2], q[3] };
            mma16(oacc[np*2    ], af, bf0);
            mma16(oacc[np*2 + 1], af, bf1);
        }
    }

#pragma unroll
    for (int nf = 0; nf < 8; ++nf) {
#pragma unroll
        for (int i = 0; i < 2; ++i) {
            int gr = r0 + g + i*8;
            if (gr >= TT) continue;
            int col = h*DD + nf*8 + tg*2;
            uint32_t w = packh2(oacc[nf][i*2 + 0], oacc[nf][i*2 + 1]);
            *(uint32_t*)&O[((size_t)b*TT + gr)*CC + col] = w;
        }
    }
}

static const int ATTN_SMEM = (128*QST + JP*KST + JP*VST) * (int)sizeof(uint32_t); // 69120
static const int GEMM_SMEM = STG * (int)STAGE_B;   // 61440

extern "C" void kernel_launch(void* const* d_in, const int* in_sizes, int n_in,
                              void* d_out, int out_size)
{
    (void)in_sizes; (void)n_in; (void)out_size;
    const float* x   = (const float*)d_in[0];
    const float* wq  = (const float*)d_in[1];
    const float* qg  = (const float*)d_in[2];
    const float* qb  = (const float*)d_in[3];
    const float* qm  = (const float*)d_in[4];
    const float* qv  = (const float*)d_in[5];
    const float* wk  = (const float*)d_in[6];
    const float* kg  = (const float*)d_in[7];
    const float* kb  = (const float*)d_in[8];
    const float* km  = (const float*)d_in[9];
    const float* kv_ = (const float*)d_in[10];
    const float* wv  = (const float*)d_in[11];
    const float* vg  = (const float*)d_in[12];
    const float* vb  = (const float*)d_in[13];
    const float* vm  = (const float*)d_in[14];
    const float* vv_ = (const float*)d_in[15];
    const float* Wq  = (const float*)d_in[16];
    const float* Wk  = (const float*)d_in[17];
    const float* Wv  = (const float*)d_in[18];
    const float* Wo  = (const float*)d_in[19];
    const float* bo  = (const float*)d_in[20];
    float* out = (float*)d_out;

    __half *qc, *kc, *vc, *Qp, *Kp, *Vp, *Op;
    uint32_t *Wqt, *Wkt, *Wvt, *Wot;
    cudaGetSymbolAddress((void**)&qc, g_qc);
    cudaGetSymbolAddress((void**)&kc, g_kc);
    cudaGetSymbolAddress((void**)&vc, g_vc);
    cudaGetSymbolAddress((void**)&Qp, g_Q);
    cudaGetSymbolAddress((void**)&Kp, g_K);
    cudaGetSymbolAddress((void**)&Vp, g_V);
    cudaGetSymbolAddress((void**)&Op, g_O);
    cudaGetSymbolAddress((void**)&Wqt, g_Wqt);
    cudaGetSymbolAddress((void**)&Wkt, g_Wkt);
    cudaGetSymbolAddress((void**)&Wvt, g_Wvt);
    cudaGetSymbolAddress((void**)&Wot, g_Wot);

    // 0. weight conversion
    dim3 wg(CC/32, CC/32, 4);
    cvt_weights<<<wg, dim3(32,32)>>>(Wq, Wk, Wv, Wo);

    // 1. fused conv projections
    dwbn_fused<<<BB*HH, CC>>>(x, wq, qg, qb, qm, qv,
                              wk, kg, kb, km, kv_,
                              wv, vg, vb, vm, vv_, qc, kc, vc);

    // 2. merged Q/K/V dense projections (one launch, 1686 blocks)
    cudaFuncSetAttribute(gemm_qkv, cudaFuncAttributeMaxDynamicSharedMemorySize, GEMM_SMEM);
    cudaFuncSetAttribute(gemm_out, cudaFuncAttributeMaxDynamicSharedMemorySize, GEMM_SMEM);
    gemm_qkv<<<1686, 256, GEMM_SMEM>>>(qc, kc, vc, Wqt, Wkt, Wvt, Qp, Kp, Vp);

    // 3. attention
    cudaFuncSetAttribute(attn_f16, cudaFuncAttributeMaxDynamicSharedMemorySize, ATTN_SMEM);
    dim3 ga((TT + 127)/128, BB*NHEAD);   // 7 x 384
    attn_f16<<<ga, 256, ATTN_SMEM>>>(Qp, Kp, Vp, Op);

    // 4. output projection (+bias, fp32 out)
    gemm_out<<<1176, 256, GEMM_SMEM>>>(Op, Wot, bo, out);
}